// round 7
// baseline (speedup 1.0000x reference)
#include <cuda_runtime.h>
#include <math.h>

#define NN 20000
#define EE 640000
#define HID 128

// ---------------- scratch (device globals; no allocation) ----------------
__device__ int   g_is64;
__device__ int   g_flag;           // scan completion counter (reset each call)
__device__ int   g_csrc[EE];       // CSR: src ids grouped by dst
__device__ int   g_icnt[NN];       // in-degree (int)
__device__ int   g_rowptr[NN + 1];
__device__ int   g_cursor[NN];
__device__ int   g_part[64];       // block partial sums for scan
__device__ float g_dinv[NN];       // rsqrt(deg+1)
__device__ float g_x  [NN * HID];
__device__ float g_h1 [NN * HID];
__device__ float g_ns [NN * HID];
__device__ float g_h2 [NN * HID];

// ---------------- small helpers ----------------
__device__ __forceinline__ float gelu_f(float x) {
    return 0.5f * x * (1.0f + erff(x * 0.70710678118654752440f));
}

// packed fp32x2 FMA (Blackwell): acc = a * b + acc, two lanes per instruction
__device__ __forceinline__ void fma2(unsigned long long& acc,
                                     unsigned long long a, unsigned long long b) {
    asm("fma.rn.f32x2 %0, %1, %2, %0;" : "+l"(acc) : "l"(a), "l"(b));
}
__device__ __forceinline__ unsigned long long dup2(float a) {
    unsigned long long r;
    asm("mov.b64 %0, {%1, %1};" : "=l"(r) : "f"(a));
    return r;
}
union F4U2 {
    float4 f;
    struct { unsigned long long lo, hi; } u;
    struct { float x, y, z, w; } s;
};

// ---------------- init: zero icnt + flag, detect edge dtype ----------------
__global__ void init_k(const int* __restrict__ ei_words, int n) {
    int idx = blockIdx.x * blockDim.x + threadIdx.x;
    int stride = gridDim.x * blockDim.x;
    for (int i = idx; i < n; i += stride) g_icnt[i] = 0;
    if (idx == 0) g_flag = 0;
    if (blockIdx.x == 0 && threadIdx.x < 64) {
        // int64 little-endian => high words of first 64 values all zero
        int hi = ei_words[2 * threadIdx.x + 1];
        __shared__ unsigned s[2];
        unsigned b = __ballot_sync(0xFFFFFFFFu, hi != 0);
        if ((threadIdx.x & 31) == 0) s[threadIdx.x >> 5] = b;
        __syncthreads();
        if (threadIdx.x == 0) g_is64 = ((s[0] | s[1]) == 0u) ? 1 : 0;
    }
}

// count in-degree (dst only)
__global__ void count_k(const void* __restrict__ ei, int E) {
    int e = blockIdx.x * blockDim.x + threadIdx.x;
    if (e >= E) return;
    int d;
    if (g_is64) d = (int)((const long long*)ei)[E + e];
    else        d = ((const int*)ei)[E + e];
    atomicAdd(&g_icnt[d], 1);
}

// ---------------- single-launch scan (20 blocks, flag-synchronized) ----------------
__global__ void __launch_bounds__(1024) scan_fused_k(int n) {
    __shared__ int wsum[32];
    __shared__ int s_off;
    int tid = threadIdx.x, lane = tid & 31, wid = tid >> 5;
    int i = blockIdx.x * 1024 + tid;
    int c = (i < n) ? g_icnt[i] : 0;
    int incl = c;
    #pragma unroll
    for (int off = 1; off < 32; off <<= 1) {
        int u = __shfl_up_sync(0xFFFFFFFFu, incl, off);
        if (lane >= off) incl += u;
    }
    if (lane == 31) wsum[wid] = incl;
    __syncthreads();
    if (wid == 0) {
        int t = wsum[lane];
        #pragma unroll
        for (int off = 1; off < 32; off <<= 1) {
            int u = __shfl_up_sync(0xFFFFFFFFu, t, off);
            if (lane >= off) t += u;
        }
        wsum[lane] = t;
    }
    __syncthreads();
    int warp_off = (wid == 0) ? 0 : wsum[wid - 1];
    int local_excl = warp_off + incl - c;
    int block_total = wsum[31];

    // publish partial, wait for all blocks
    if (tid == 0) {
        g_part[blockIdx.x] = block_total;
        __threadfence();
        atomicAdd(&g_flag, 1);
        while (atomicAdd(&g_flag, 0) < (int)gridDim.x) { }
        __threadfence();
        int o = 0;
        for (int b = 0; b < (int)blockIdx.x; b++) o += g_part[b];
        s_off = o;
        if (blockIdx.x == gridDim.x - 1) g_rowptr[n] = o + block_total;
    }
    __syncthreads();
    int run = s_off + local_excl;
    if (i < n) {
        g_rowptr[i] = run;
        g_cursor[i] = run;
        g_dinv[i]   = rsqrtf((float)c + 1.0f);
    }
}

// CSR fill (separate launch — atomics must not co-run with GEMM)
__global__ void fill_k(const void* __restrict__ ei, int E) {
    int e = blockIdx.x * blockDim.x + threadIdx.x;
    if (e >= E) return;
    int s, d;
    if (g_is64) {
        const long long* p = (const long long*)ei;
        s = (int)p[e]; d = (int)p[E + e];
    } else {
        const int* p = (const int*)ei;
        s = p[e]; d = p[E + e];
    }
    int slot = atomicAdd(&g_cursor[d], 1);
    g_csrc[slot] = s;
}

// ---------------- GEMM (TN=4, CT=32: warp-uniform A loads) ----------------
template<int BN, int ACT>
__global__ void __launch_bounds__(256) gemm_k(
    const float* __restrict__ A, const float* __restrict__ W,
    const float* __restrict__ bias, float* __restrict__ C, int nrows)
{
    constexpr int TN  = 4;
    constexpr int CT  = BN / TN;
    constexpr int RT  = 256 / CT;
    constexpr int BM  = 32;
    constexpr int RPT = BM / RT;
    const int tid  = threadIdx.x;
    const int tc   = tid % CT;
    const int tr   = tid / CT;
    const int row0 = blockIdx.x * BM + tr * RPT;
    const int col0 = tc * TN;
    if (row0 >= nrows) return;

    unsigned long long acc[RPT][2];
    #pragma unroll
    for (int r = 0; r < RPT; r++) { acc[r][0] = 0ull; acc[r][1] = 0ull; }

    for (int k4 = 0; k4 < 128; k4 += 4) {
        F4U2 w0, w1, w2, w3;
        w0.f = *(const float4*)&W[(k4 + 0) * BN + col0];
        w1.f = *(const float4*)&W[(k4 + 1) * BN + col0];
        w2.f = *(const float4*)&W[(k4 + 2) * BN + col0];
        w3.f = *(const float4*)&W[(k4 + 3) * BN + col0];
        #pragma unroll
        for (int r = 0; r < RPT; r++) {
            F4U2 a;
            a.f = *(const float4*)&A[(size_t)(row0 + r) * 128 + k4];
            unsigned long long ax = dup2(a.s.x), ay = dup2(a.s.y),
                               az = dup2(a.s.z), aw = dup2(a.s.w);
            fma2(acc[r][0], ax, w0.u.lo); fma2(acc[r][1], ax, w0.u.hi);
            fma2(acc[r][0], ay, w1.u.lo); fma2(acc[r][1], ay, w1.u.hi);
            fma2(acc[r][0], az, w2.u.lo); fma2(acc[r][1], az, w2.u.hi);
            fma2(acc[r][0], aw, w3.u.lo); fma2(acc[r][1], aw, w3.u.hi);
        }
    }

    #pragma unroll
    for (int r = 0; r < RPT; r++) {
        F4U2 o;
        o.u.lo = acc[r][0]; o.u.hi = acc[r][1];
        float v[4] = {o.s.x, o.s.y, o.s.z, o.s.w};
        #pragma unroll
        for (int c = 0; c < TN; c++) {
            float t = v[c];
            if (bias) t += bias[col0 + c];
            if (ACT == 1) t = fmaxf(t, 0.0f);
            if (ACT == 2) t = gelu_f(t);
            v[c] = t;
        }
        o.s.x = v[0]; o.s.y = v[1]; o.s.z = v[2]; o.s.w = v[3];
        *(float4*)&C[(size_t)(row0 + r) * BN + col0] = o.f;
    }
}

// ---------------- GCN gather (float4/lane): h1 = relu(sum + selfloop + b)
__global__ void gcn_gather_k(const float* __restrict__ bias, int n) {
    int node = blockIdx.x * (blockDim.x >> 5) + (threadIdx.x >> 5);
    if (node >= n) return;
    int lane = threadIdx.x & 31;
    int beg = g_rowptr[node], end = g_rowptr[node + 1];
    float dd = g_dinv[node];
    const float4* xd = (const float4*)(g_x + (size_t)node * HID);
    float4 sv = xd[lane];
    float sl = dd * dd;
    float4 acc;
    acc.x = sv.x * sl; acc.y = sv.y * sl; acc.z = sv.z * sl; acc.w = sv.w * sl;

    int e = beg;
    for (; e + 1 < end; e += 2) {
        int s0 = g_csrc[e], s1 = g_csrc[e + 1];
        float c0 = g_dinv[s0] * dd, c1 = g_dinv[s1] * dd;
        float4 v0 = ((const float4*)(g_x + (size_t)s0 * HID))[lane];
        float4 v1 = ((const float4*)(g_x + (size_t)s1 * HID))[lane];
        acc.x = fmaf(v0.x, c0, acc.x); acc.y = fmaf(v0.y, c0, acc.y);
        acc.z = fmaf(v0.z, c0, acc.z); acc.w = fmaf(v0.w, c0, acc.w);
        acc.x = fmaf(v1.x, c1, acc.x); acc.y = fmaf(v1.y, c1, acc.y);
        acc.z = fmaf(v1.z, c1, acc.z); acc.w = fmaf(v1.w, c1, acc.w);
    }
    if (e < end) {
        int s0 = g_csrc[e];
        float c0 = g_dinv[s0] * dd;
        float4 v0 = ((const float4*)(g_x + (size_t)s0 * HID))[lane];
        acc.x = fmaf(v0.x, c0, acc.x); acc.y = fmaf(v0.y, c0, acc.y);
        acc.z = fmaf(v0.z, c0, acc.z); acc.w = fmaf(v0.w, c0, acc.w);
    }
    float4 b4 = ((const float4*)bias)[lane];
    float4 o;
    o.x = fmaxf(acc.x + b4.x, 0.0f);
    o.y = fmaxf(acc.y + b4.y, 0.0f);
    o.z = fmaxf(acc.z + b4.z, 0.0f);
    o.w = fmaxf(acc.w + b4.w, 0.0f);
    ((float4*)(g_h1 + (size_t)node * HID))[lane] = o;
}

// ---------------- SAGE gather (float4/lane): ns = mean_neigh h1[s]
__global__ void sage_gather_k(int n) {
    int node = blockIdx.x * (blockDim.x >> 5) + (threadIdx.x >> 5);
    if (node >= n) return;
    int lane = threadIdx.x & 31;
    int beg = g_rowptr[node], end = g_rowptr[node + 1];
    float4 acc = make_float4(0.f, 0.f, 0.f, 0.f);
    int e = beg;
    for (; e + 1 < end; e += 2) {
        int s0 = g_csrc[e], s1 = g_csrc[e + 1];
        float4 v0 = ((const float4*)(g_h1 + (size_t)s0 * HID))[lane];
        float4 v1 = ((const float4*)(g_h1 + (size_t)s1 * HID))[lane];
        acc.x += v0.x + v1.x; acc.y += v0.y + v1.y;
        acc.z += v0.z + v1.z; acc.w += v0.w + v1.w;
    }
    if (e < end) {
        int s0 = g_csrc[e];
        float4 v0 = ((const float4*)(g_h1 + (size_t)s0 * HID))[lane];
        acc.x += v0.x; acc.y += v0.y; acc.z += v0.z; acc.w += v0.w;
    }
    int deg = end - beg;
    float inv = 1.0f / (float)max(deg, 1);
    acc.x *= inv; acc.y *= inv; acc.z *= inv; acc.w *= inv;
    ((float4*)(g_ns + (size_t)node * HID))[lane] = acc;
}

// fused SAGE GEMM + value head: h2 = relu(ns@Wl + h1@Wr + bl); values = h2@Wv + bv
__global__ void __launch_bounds__(256) gemm2_k(
    const float* __restrict__ A1, const float* __restrict__ W1,
    const float* __restrict__ A2, const float* __restrict__ W2,
    const float* __restrict__ bias,
    float* __restrict__ C, int nrows,
    const float* __restrict__ Wv, const float* __restrict__ bv,
    float* __restrict__ values_out)
{
    constexpr int BN = 128, TN = 4, CT = 32, RPT = 4, BM = 32;
    const int tid  = threadIdx.x;
    const int tc   = tid % CT;       // == lane
    const int tr   = tid / CT;       // == warp
    const int row0 = blockIdx.x * BM + tr * RPT;
    const int col0 = tc * TN;
    if (row0 >= nrows) return;

    unsigned long long acc[RPT][2];
    #pragma unroll
    for (int r = 0; r < RPT; r++) { acc[r][0] = 0ull; acc[r][1] = 0ull; }

    #pragma unroll 1
    for (int pass = 0; pass < 2; pass++) {
        const float* A = pass ? A2 : A1;
        const float* W = pass ? W2 : W1;
        for (int k4 = 0; k4 < 128; k4 += 4) {
            F4U2 w0, w1, w2, w3;
            w0.f = *(const float4*)&W[(k4 + 0) * BN + col0];
            w1.f = *(const float4*)&W[(k4 + 1) * BN + col0];
            w2.f = *(const float4*)&W[(k4 + 2) * BN + col0];
            w3.f = *(const float4*)&W[(k4 + 3) * BN + col0];
            #pragma unroll
            for (int r = 0; r < RPT; r++) {
                F4U2 a;
                a.f = *(const float4*)&A[(size_t)(row0 + r) * 128 + k4];
                unsigned long long ax = dup2(a.s.x), ay = dup2(a.s.y),
                                   az = dup2(a.s.z), aw = dup2(a.s.w);
                fma2(acc[r][0], ax, w0.u.lo); fma2(acc[r][1], ax, w0.u.hi);
                fma2(acc[r][0], ay, w1.u.lo); fma2(acc[r][1], ay, w1.u.hi);
                fma2(acc[r][0], az, w2.u.lo); fma2(acc[r][1], az, w2.u.hi);
                fma2(acc[r][0], aw, w3.u.lo); fma2(acc[r][1], aw, w3.u.hi);
            }
        }
    }

    float4 wv = *(const float4*)&Wv[col0];
    float bv0 = bv[0];
    #pragma unroll
    for (int r = 0; r < RPT; r++) {
        F4U2 o;
        o.u.lo = acc[r][0]; o.u.hi = acc[r][1];
        o.s.x = fmaxf(o.s.x + bias[col0 + 0], 0.0f);
        o.s.y = fmaxf(o.s.y + bias[col0 + 1], 0.0f);
        o.s.z = fmaxf(o.s.z + bias[col0 + 2], 0.0f);
        o.s.w = fmaxf(o.s.w + bias[col0 + 3], 0.0f);
        *(float4*)&C[(size_t)(row0 + r) * BN + col0] = o.f;
        // value-head partial: dot of this row with Wv across the warp
        float p = fmaf(o.s.x, wv.x, fmaf(o.s.y, wv.y,
                  fmaf(o.s.z, wv.z, o.s.w * wv.w)));
        #pragma unroll
        for (int off = 16; off > 0; off >>= 1)
            p += __shfl_xor_sync(0xFFFFFFFFu, p, off);
        if (tc == 0) values_out[row0 + r] = p + bv0;
    }
}

// ---------------- launch ----------------
extern "C" void kernel_launch(void* const* d_in, const int* in_sizes, int n_in,
                              void* d_out, int out_size)
{
    const float* feat     = (const float*)d_in[0];
    const void*  ei       = d_in[1];
    const float* W_gcn    = (const float*)d_in[2];
    const float* b_gcn    = (const float*)d_in[3];
    const float* W_sage_l = (const float*)d_in[4];
    const float* b_sage_l = (const float*)d_in[5];
    const float* W_sage_r = (const float*)d_in[6];
    const float* W1       = (const float*)d_in[7];
    const float* b1       = (const float*)d_in[8];
    const float* W2       = (const float*)d_in[9];
    const float* b2       = (const float*)d_in[10];
    const float* W3       = (const float*)d_in[11];
    const float* b3       = (const float*)d_in[12];
    const float* Wv       = (const float*)d_in[13];
    const float* bv       = (const float*)d_in[14];

    const int N = in_sizes[0] / HID;   // 20000
    const int E = in_sizes[1] / 2;     // 640000

    float* means_out  = (float*)d_out;            // [N, 64]
    float* values_out = (float*)d_out + (size_t)N * 64;

    float *p_x, *p_h1, *p_ns, *p_h2;
    cudaGetSymbolAddress((void**)&p_x,  g_x);
    cudaGetSymbolAddress((void**)&p_h1, g_h1);
    cudaGetSymbolAddress((void**)&p_ns, g_ns);
    cudaGetSymbolAddress((void**)&p_h2, g_h2);

    const int TB = 256;
    const int e_blocks    = (E + TB - 1) / TB;
    const int nw_blocks   = (N * 32 + TB - 1) / TB;  // warp per node
    const int scan_blocks = (N + 1023) / 1024;       // 20
    const int gemm_blocks = (N + 31) / 32;           // 625

    // 1) init (zero icnt+flag, detect dtype)
    init_k<<<80, TB>>>((const int*)ei, N);
    // 2) in-degree count
    count_k<<<e_blocks, TB>>>(ei, E);
    // 3) single-launch synchronized scan -> rowptr/cursor/dinv
    scan_fused_k<<<scan_blocks, 1024>>>(N);
    // 4) CSR fill (isolated: contended atomics must not co-run with GEMM)
    fill_k<<<e_blocks, TB>>>(ei, E);
    // 5) GEMM1: x = feat @ W_gcn
    gemm_k<128, 0><<<gemm_blocks, TB>>>(feat, W_gcn, nullptr, p_x, N);
    // 6) GCN gather (+selfloop+bias+relu)
    gcn_gather_k<<<nw_blocks, TB>>>(b_gcn, N);
    // 7) SAGE gather (mean)
    sage_gather_k<<<nw_blocks, TB>>>(N);
    // 8) fused SAGE GEMM + value head
    gemm2_k<<<gemm_blocks, TB>>>(p_ns, W_sage_l, p_h1, W_sage_r, b_sage_l,
                                 p_h2, N, Wv, bv, values_out);
    // 9-11) policy MLP
    gemm_k<128, 2><<<gemm_blocks, TB>>>(p_h2, W1, b1, p_x, N);
    gemm_k<128, 2><<<gemm_blocks, TB>>>(p_x, W2, b2, p_ns, N);
    gemm_k<64, 0><<<gemm_blocks, TB>>>(p_ns, W3, b3, means_out, N);
}

// round 8
// speedup vs baseline: 1.0086x; 1.0086x over previous
#include <cuda_runtime.h>
#include <math.h>

#define NN 20000
#define EE 640000
#define HID 128

// ---------------- scratch (device globals; no allocation) ----------------
__device__ int   g_is64;
__device__ int   g_flag;           // scan completion counter (reset each call)
__device__ int   g_src[EE];
__device__ int   g_dst[EE];
__device__ int   g_csrc[EE];       // CSR: src ids grouped by dst
__device__ int   g_icnt[NN];       // in-degree (int)
__device__ int   g_rowptr[NN + 1];
__device__ int   g_cursor[NN];
__device__ int   g_part[64];       // block partial sums for scan
__device__ float g_dinv[NN];       // rsqrt(deg+1)
__device__ float g_x  [NN * HID];
__device__ float g_h1 [NN * HID];
__device__ float g_ns [NN * HID];
__device__ float g_h2 [NN * HID];

// ---------------- small helpers ----------------
__device__ __forceinline__ float gelu_f(float x) {
    return 0.5f * x * (1.0f + erff(x * 0.70710678118654752440f));
}

// packed fp32x2 FMA (Blackwell): acc = a * b + acc, two lanes per instruction
__device__ __forceinline__ void fma2(unsigned long long& acc,
                                     unsigned long long a, unsigned long long b) {
    asm("fma.rn.f32x2 %0, %1, %2, %0;" : "+l"(acc) : "l"(a), "l"(b));
}
__device__ __forceinline__ unsigned long long dup2(float a) {
    unsigned long long r;
    asm("mov.b64 %0, {%1, %1};" : "=l"(r) : "f"(a));
    return r;
}
union F4U2 {
    float4 f;
    struct { unsigned long long lo, hi; } u;
    struct { float x, y, z, w; } s;
};

// ---------------- init: zero icnt + flag, detect edge dtype ----------------
__global__ void init_k(const int* __restrict__ ei_words, int n) {
    int idx = blockIdx.x * blockDim.x + threadIdx.x;
    int stride = gridDim.x * blockDim.x;
    for (int i = idx; i < n; i += stride) g_icnt[i] = 0;
    if (idx == 0) g_flag = 0;
    if (blockIdx.x == 0 && threadIdx.x < 64) {
        // int64 little-endian => high words of first 64 values all zero
        int hi = ei_words[2 * threadIdx.x + 1];
        __shared__ unsigned s[2];
        unsigned b = __ballot_sync(0xFFFFFFFFu, hi != 0);
        if ((threadIdx.x & 31) == 0) s[threadIdx.x >> 5] = b;
        __syncthreads();
        if (threadIdx.x == 0) g_is64 = ((s[0] | s[1]) == 0u) ? 1 : 0;
    }
}

// convert edge index to staged int32 + count in-degree (R5-proven)
__global__ void convert_count_k(const void* __restrict__ ei, int E) {
    int e = blockIdx.x * blockDim.x + threadIdx.x;
    if (e >= E) return;
    int s, d;
    if (g_is64) {
        const long long* p = (const long long*)ei;
        s = (int)p[e]; d = (int)p[E + e];
    } else {
        const int* p = (const int*)ei;
        s = p[e]; d = p[E + e];
    }
    g_src[e] = s;
    g_dst[e] = d;
    atomicAdd(&g_icnt[d], 1);
}

// ---------------- single-launch scan (20 blocks, flag-synchronized) ----------------
__global__ void __launch_bounds__(1024) scan_fused_k(int n) {
    __shared__ int wsum[32];
    __shared__ int s_off;
    int tid = threadIdx.x, lane = tid & 31, wid = tid >> 5;
    int i = blockIdx.x * 1024 + tid;
    int c = (i < n) ? g_icnt[i] : 0;
    int incl = c;
    #pragma unroll
    for (int off = 1; off < 32; off <<= 1) {
        int u = __shfl_up_sync(0xFFFFFFFFu, incl, off);
        if (lane >= off) incl += u;
    }
    if (lane == 31) wsum[wid] = incl;
    __syncthreads();
    if (wid == 0) {
        int t = wsum[lane];
        #pragma unroll
        for (int off = 1; off < 32; off <<= 1) {
            int u = __shfl_up_sync(0xFFFFFFFFu, t, off);
            if (lane >= off) t += u;
        }
        wsum[lane] = t;
    }
    __syncthreads();
    int warp_off = (wid == 0) ? 0 : wsum[wid - 1];
    int local_excl = warp_off + incl - c;
    int block_total = wsum[31];

    if (tid == 0) {
        g_part[blockIdx.x] = block_total;
        __threadfence();
        atomicAdd(&g_flag, 1);
        while (atomicAdd(&g_flag, 0) < (int)gridDim.x) { }
        __threadfence();
        int o = 0;
        for (int b = 0; b < (int)blockIdx.x; b++) o += g_part[b];
        s_off = o;
        if (blockIdx.x == gridDim.x - 1) g_rowptr[n] = o + block_total;
    }
    __syncthreads();
    int run = s_off + local_excl;
    if (i < n) {
        g_rowptr[i] = run;
        g_cursor[i] = run;
        g_dinv[i]   = rsqrtf((float)c + 1.0f);
    }
}

// ---------------- GEMM body (TN=4, CT=32: warp-uniform A loads) ----------------
template<int BN, int ACT>
__device__ __forceinline__ void gemm_body(
    const float* __restrict__ A, const float* __restrict__ W,
    const float* __restrict__ bias, float* __restrict__ C,
    int nrows, int bid)
{
    constexpr int TN  = 4;
    constexpr int CT  = BN / TN;
    constexpr int RT  = 256 / CT;
    constexpr int BM  = 32;
    constexpr int RPT = BM / RT;
    const int tid  = threadIdx.x;
    const int tc   = tid % CT;
    const int tr   = tid / CT;
    const int row0 = bid * BM + tr * RPT;
    const int col0 = tc * TN;
    if (row0 >= nrows) return;

    unsigned long long acc[RPT][2];
    #pragma unroll
    for (int r = 0; r < RPT; r++) { acc[r][0] = 0ull; acc[r][1] = 0ull; }

    for (int k4 = 0; k4 < 128; k4 += 4) {
        F4U2 w0, w1, w2, w3;
        w0.f = *(const float4*)&W[(k4 + 0) * BN + col0];
        w1.f = *(const float4*)&W[(k4 + 1) * BN + col0];
        w2.f = *(const float4*)&W[(k4 + 2) * BN + col0];
        w3.f = *(const float4*)&W[(k4 + 3) * BN + col0];
        #pragma unroll
        for (int r = 0; r < RPT; r++) {
            F4U2 a;
            a.f = *(const float4*)&A[(size_t)(row0 + r) * 128 + k4];
            unsigned long long ax = dup2(a.s.x), ay = dup2(a.s.y),
                               az = dup2(a.s.z), aw = dup2(a.s.w);
            fma2(acc[r][0], ax, w0.u.lo); fma2(acc[r][1], ax, w0.u.hi);
            fma2(acc[r][0], ay, w1.u.lo); fma2(acc[r][1], ay, w1.u.hi);
            fma2(acc[r][0], az, w2.u.lo); fma2(acc[r][1], az, w2.u.hi);
            fma2(acc[r][0], aw, w3.u.lo); fma2(acc[r][1], aw, w3.u.hi);
        }
    }

    #pragma unroll
    for (int r = 0; r < RPT; r++) {
        F4U2 o;
        o.u.lo = acc[r][0]; o.u.hi = acc[r][1];
        float v[4] = {o.s.x, o.s.y, o.s.z, o.s.w};
        #pragma unroll
        for (int c = 0; c < TN; c++) {
            float t = v[c];
            if (bias) t += bias[col0 + c];
            if (ACT == 1) t = fmaxf(t, 0.0f);
            if (ACT == 2) t = gelu_f(t);
            v[c] = t;
        }
        o.s.x = v[0]; o.s.y = v[1]; o.s.z = v[2]; o.s.w = v[3];
        *(float4*)&C[(size_t)(row0 + r) * BN + col0] = o.f;
    }
}

template<int BN, int ACT>
__global__ void __launch_bounds__(256) gemm_k(
    const float* __restrict__ A, const float* __restrict__ W,
    const float* __restrict__ bias, float* __restrict__ C, int nrows)
{
    gemm_body<BN, ACT>(A, W, bias, C, nrows, blockIdx.x);
}

// fused: blocks [0, gb) do GEMM1 (feat@W_gcn); blocks [gb, ..) do CSR fill
// (fill reads staged int32 arrays; atomics hide under GEMM FMA work)
__global__ void __launch_bounds__(256) gemm1_fill_k(
    const float* __restrict__ A, const float* __restrict__ W,
    float* __restrict__ C, int nrows, int gb, int E)
{
    if ((int)blockIdx.x < gb) {
        gemm_body<128, 0>(A, W, nullptr, C, nrows, blockIdx.x);
    } else {
        int e = (blockIdx.x - gb) * 256 + threadIdx.x;
        if (e >= E) return;
        int d = g_dst[e];
        int slot = atomicAdd(&g_cursor[d], 1);
        g_csrc[slot] = g_src[e];
    }
}

// ---------------- GCN gather (scalar, 2-edge unroll, MLP=8 — R5-proven)
__global__ void gcn_gather_k(const float* __restrict__ bias, int n) {
    int node = blockIdx.x * (blockDim.x >> 5) + (threadIdx.x >> 5);
    if (node >= n) return;
    int lane = threadIdx.x & 31;
    int beg = g_rowptr[node], end = g_rowptr[node + 1];
    float dd = g_dinv[node];
    const float* xd = g_x + (size_t)node * HID;
    float sl = dd * dd;
    float a0 = xd[lane] * sl;
    float a1 = xd[lane + 32] * sl;
    float a2 = xd[lane + 64] * sl;
    float a3 = xd[lane + 96] * sl;

    int e = beg;
    for (; e + 1 < end; e += 2) {
        int s0 = g_csrc[e], s1 = g_csrc[e + 1];
        float c0 = g_dinv[s0] * dd, c1 = g_dinv[s1] * dd;
        const float* x0 = g_x + (size_t)s0 * HID;
        const float* x1 = g_x + (size_t)s1 * HID;
        float v00 = x0[lane],      v01 = x1[lane];
        float v10 = x0[lane + 32], v11 = x1[lane + 32];
        float v20 = x0[lane + 64], v21 = x1[lane + 64];
        float v30 = x0[lane + 96], v31 = x1[lane + 96];
        a0 = fmaf(v00, c0, a0); a0 = fmaf(v01, c1, a0);
        a1 = fmaf(v10, c0, a1); a1 = fmaf(v11, c1, a1);
        a2 = fmaf(v20, c0, a2); a2 = fmaf(v21, c1, a2);
        a3 = fmaf(v30, c0, a3); a3 = fmaf(v31, c1, a3);
    }
    if (e < end) {
        int s0 = g_csrc[e];
        float c0 = g_dinv[s0] * dd;
        const float* x0 = g_x + (size_t)s0 * HID;
        a0 = fmaf(x0[lane],      c0, a0);
        a1 = fmaf(x0[lane + 32], c0, a1);
        a2 = fmaf(x0[lane + 64], c0, a2);
        a3 = fmaf(x0[lane + 96], c0, a3);
    }
    float* out = g_h1 + (size_t)node * HID;
    out[lane]      = fmaxf(a0 + bias[lane],      0.0f);
    out[lane + 32] = fmaxf(a1 + bias[lane + 32], 0.0f);
    out[lane + 64] = fmaxf(a2 + bias[lane + 64], 0.0f);
    out[lane + 96] = fmaxf(a3 + bias[lane + 96], 0.0f);
}

// ---------------- SAGE gather (scalar, 2-edge unroll — R5-proven)
__global__ void sage_gather_k(int n) {
    int node = blockIdx.x * (blockDim.x >> 5) + (threadIdx.x >> 5);
    if (node >= n) return;
    int lane = threadIdx.x & 31;
    int beg = g_rowptr[node], end = g_rowptr[node + 1];
    float a0 = 0.f, a1 = 0.f, a2 = 0.f, a3 = 0.f;
    int e = beg;
    for (; e + 1 < end; e += 2) {
        int s0 = g_csrc[e], s1 = g_csrc[e + 1];
        const float* x0 = g_h1 + (size_t)s0 * HID;
        const float* x1 = g_h1 + (size_t)s1 * HID;
        a0 += x0[lane];      a0 += x1[lane];
        a1 += x0[lane + 32]; a1 += x1[lane + 32];
        a2 += x0[lane + 64]; a2 += x1[lane + 64];
        a3 += x0[lane + 96]; a3 += x1[lane + 96];
    }
    if (e < end) {
        int s0 = g_csrc[e];
        const float* x0 = g_h1 + (size_t)s0 * HID;
        a0 += x0[lane]; a1 += x0[lane + 32]; a2 += x0[lane + 64]; a3 += x0[lane + 96];
    }
    int deg = end - beg;
    float inv = 1.0f / (float)max(deg, 1);
    float* out = g_ns + (size_t)node * HID;
    out[lane]      = a0 * inv;
    out[lane + 32] = a1 * inv;
    out[lane + 64] = a2 * inv;
    out[lane + 96] = a3 * inv;
}

// fused SAGE GEMM + value head: h2 = relu(ns@Wl + h1@Wr + bl); values = h2@Wv + bv
__global__ void __launch_bounds__(256) gemm2_k(
    const float* __restrict__ A1, const float* __restrict__ W1,
    const float* __restrict__ A2, const float* __restrict__ W2,
    const float* __restrict__ bias,
    float* __restrict__ C, int nrows,
    const float* __restrict__ Wv, const float* __restrict__ bv,
    float* __restrict__ values_out)
{
    constexpr int BN = 128, TN = 4, CT = 32, RPT = 4, BM = 32;
    const int tid  = threadIdx.x;
    const int tc   = tid % CT;       // == lane
    const int tr   = tid / CT;       // == warp
    const int row0 = blockIdx.x * BM + tr * RPT;
    const int col0 = tc * TN;
    if (row0 >= nrows) return;

    unsigned long long acc[RPT][2];
    #pragma unroll
    for (int r = 0; r < RPT; r++) { acc[r][0] = 0ull; acc[r][1] = 0ull; }

    #pragma unroll 1
    for (int pass = 0; pass < 2; pass++) {
        const float* A = pass ? A2 : A1;
        const float* W = pass ? W2 : W1;
        for (int k4 = 0; k4 < 128; k4 += 4) {
            F4U2 w0, w1, w2, w3;
            w0.f = *(const float4*)&W[(k4 + 0) * BN + col0];
            w1.f = *(const float4*)&W[(k4 + 1) * BN + col0];
            w2.f = *(const float4*)&W[(k4 + 2) * BN + col0];
            w3.f = *(const float4*)&W[(k4 + 3) * BN + col0];
            #pragma unroll
            for (int r = 0; r < RPT; r++) {
                F4U2 a;
                a.f = *(const float4*)&A[(size_t)(row0 + r) * 128 + k4];
                unsigned long long ax = dup2(a.s.x), ay = dup2(a.s.y),
                                   az = dup2(a.s.z), aw = dup2(a.s.w);
                fma2(acc[r][0], ax, w0.u.lo); fma2(acc[r][1], ax, w0.u.hi);
                fma2(acc[r][0], ay, w1.u.lo); fma2(acc[r][1], ay, w1.u.hi);
                fma2(acc[r][0], az, w2.u.lo); fma2(acc[r][1], az, w2.u.hi);
                fma2(acc[r][0], aw, w3.u.lo); fma2(acc[r][1], aw, w3.u.hi);
            }
        }
    }

    float4 wv = *(const float4*)&Wv[col0];
    float bv0 = bv[0];
    #pragma unroll
    for (int r = 0; r < RPT; r++) {
        F4U2 o;
        o.u.lo = acc[r][0]; o.u.hi = acc[r][1];
        o.s.x = fmaxf(o.s.x + bias[col0 + 0], 0.0f);
        o.s.y = fmaxf(o.s.y + bias[col0 + 1], 0.0f);
        o.s.z = fmaxf(o.s.z + bias[col0 + 2], 0.0f);
        o.s.w = fmaxf(o.s.w + bias[col0 + 3], 0.0f);
        *(float4*)&C[(size_t)(row0 + r) * BN + col0] = o.f;
        float p = fmaf(o.s.x, wv.x, fmaf(o.s.y, wv.y,
                  fmaf(o.s.z, wv.z, o.s.w * wv.w)));
        #pragma unroll
        for (int off = 16; off > 0; off >>= 1)
            p += __shfl_xor_sync(0xFFFFFFFFu, p, off);
        if (tc == 0) values_out[row0 + r] = p + bv0;
    }
}

// ---------------- launch ----------------
extern "C" void kernel_launch(void* const* d_in, const int* in_sizes, int n_in,
                              void* d_out, int out_size)
{
    const float* feat     = (const float*)d_in[0];
    const void*  ei       = d_in[1];
    const float* W_gcn    = (const float*)d_in[2];
    const float* b_gcn    = (const float*)d_in[3];
    const float* W_sage_l = (const float*)d_in[4];
    const float* b_sage_l = (const float*)d_in[5];
    const float* W_sage_r = (const float*)d_in[6];
    const float* W1       = (const float*)d_in[7];
    const float* b1       = (const float*)d_in[8];
    const float* W2       = (const float*)d_in[9];
    const float* b2       = (const float*)d_in[10];
    const float* W3       = (const float*)d_in[11];
    const float* b3       = (const float*)d_in[12];
    const float* Wv       = (const float*)d_in[13];
    const float* bv       = (const float*)d_in[14];

    const int N = in_sizes[0] / HID;   // 20000
    const int E = in_sizes[1] / 2;     // 640000

    float* means_out  = (float*)d_out;            // [N, 64]
    float* values_out = (float*)d_out + (size_t)N * 64;

    float *p_x, *p_h1, *p_ns, *p_h2;
    cudaGetSymbolAddress((void**)&p_x,  g_x);
    cudaGetSymbolAddress((void**)&p_h1, g_h1);
    cudaGetSymbolAddress((void**)&p_ns, g_ns);
    cudaGetSymbolAddress((void**)&p_h2, g_h2);

    const int TB = 256;
    const int e_blocks    = (E + TB - 1) / TB;       // 2500
    const int nw_blocks   = (N * 32 + TB - 1) / TB;  // warp per node
    const int scan_blocks = (N + 1023) / 1024;       // 20
    const int gemm_blocks = (N + 31) / 32;           // 625

    // 1) init (zero icnt+flag, detect dtype)
    init_k<<<80, TB>>>((const int*)ei, N);
    // 2) convert to staged int32 + in-degree count
    convert_count_k<<<e_blocks, TB>>>(ei, E);
    // 3) single-launch synchronized scan -> rowptr/cursor/dinv
    scan_fused_k<<<scan_blocks, 1024>>>(N);
    // 4) GEMM1 (feat@W_gcn) co-running with CSR fill (staged int32)
    gemm1_fill_k<<<gemm_blocks + e_blocks, TB>>>(feat, W_gcn, p_x, N,
                                                 gemm_blocks, E);
    // 5) GCN gather (+selfloop+bias+relu)
    gcn_gather_k<<<nw_blocks, TB>>>(b_gcn, N);
    // 6) SAGE gather (mean)
    sage_gather_k<<<nw_blocks, TB>>>(N);
    // 7) fused SAGE GEMM + value head
    gemm2_k<<<gemm_blocks, TB>>>(p_ns, W_sage_l, p_h1, W_sage_r, b_sage_l,
                                 p_h2, N, Wv, bv, values_out);
    // 8-10) policy MLP
    gemm_k<128, 2><<<gemm_blocks, TB>>>(p_h2, W1, b1, p_x, N);
    gemm_k<128, 2><<<gemm_blocks, TB>>>(p_x, W2, b2, p_ns, N);
    gemm_k<64, 0><<<gemm_blocks, TB>>>(p_ns, W3, b3, means_out, N);
}

// round 9
// speedup vs baseline: 1.0105x; 1.0019x over previous
#include <cuda_runtime.h>
#include <math.h>

#define NN 20000
#define EE 640000
#define HID 128

// ---------------- scratch (device globals; no allocation) ----------------
__device__ int   g_is64;
__device__ int   g_flag;
__device__ int   g_src[EE];
__device__ int   g_dst[EE];
__device__ int   g_csrc[EE];
__device__ int   g_icnt[NN];
__device__ int   g_rowptr[NN + 1];
__device__ int   g_cursor[NN];
__device__ int   g_part[64];
__device__ float g_dinv[NN];
__device__ float g_x  [NN * HID];
__device__ float g_h1 [NN * HID];
__device__ float g_ns [NN * HID];
__device__ float g_h2 [NN * HID];

// ---------------- small helpers ----------------
__device__ __forceinline__ float gelu_f(float x) {
    return 0.5f * x * (1.0f + erff(x * 0.70710678118654752440f));
}
__device__ __forceinline__ void fma2(unsigned long long& acc,
                                     unsigned long long a, unsigned long long b) {
    asm("fma.rn.f32x2 %0, %1, %2, %0;" : "+l"(acc) : "l"(a), "l"(b));
}
__device__ __forceinline__ unsigned long long dup2(float a) {
    unsigned long long r;
    asm("mov.b64 %0, {%1, %1};" : "=l"(r) : "f"(a));
    return r;
}
union F4U2 {
    float4 f;
    struct { unsigned long long lo, hi; } u;
    struct { float x, y, z, w; } s;
};

// ---------------- init ----------------
__global__ void init_k(const int* __restrict__ ei_words, int n) {
    int idx = blockIdx.x * blockDim.x + threadIdx.x;
    int stride = gridDim.x * blockDim.x;
    for (int i = idx; i < n; i += stride) g_icnt[i] = 0;
    if (idx == 0) g_flag = 0;
    if (blockIdx.x == 0 && threadIdx.x < 64) {
        int hi = ei_words[2 * threadIdx.x + 1];
        __shared__ unsigned s[2];
        unsigned b = __ballot_sync(0xFFFFFFFFu, hi != 0);
        if ((threadIdx.x & 31) == 0) s[threadIdx.x >> 5] = b;
        __syncthreads();
        if (threadIdx.x == 0) g_is64 = ((s[0] | s[1]) == 0u) ? 1 : 0;
    }
}

__global__ void convert_count_k(const void* __restrict__ ei, int E) {
    int e = blockIdx.x * blockDim.x + threadIdx.x;
    if (e >= E) return;
    int s, d;
    if (g_is64) {
        const long long* p = (const long long*)ei;
        s = (int)p[e]; d = (int)p[E + e];
    } else {
        const int* p = (const int*)ei;
        s = p[e]; d = p[E + e];
    }
    g_src[e] = s;
    g_dst[e] = d;
    atomicAdd(&g_icnt[d], 1);
}

// ---------------- single-launch scan ----------------
__global__ void __launch_bounds__(1024) scan_fused_k(int n) {
    __shared__ int wsum[32];
    __shared__ int s_off;
    int tid = threadIdx.x, lane = tid & 31, wid = tid >> 5;
    int i = blockIdx.x * 1024 + tid;
    int c = (i < n) ? g_icnt[i] : 0;
    int incl = c;
    #pragma unroll
    for (int off = 1; off < 32; off <<= 1) {
        int u = __shfl_up_sync(0xFFFFFFFFu, incl, off);
        if (lane >= off) incl += u;
    }
    if (lane == 31) wsum[wid] = incl;
    __syncthreads();
    if (wid == 0) {
        int t = wsum[lane];
        #pragma unroll
        for (int off = 1; off < 32; off <<= 1) {
            int u = __shfl_up_sync(0xFFFFFFFFu, t, off);
            if (lane >= off) t += u;
        }
        wsum[lane] = t;
    }
    __syncthreads();
    int warp_off = (wid == 0) ? 0 : wsum[wid - 1];
    int local_excl = warp_off + incl - c;
    int block_total = wsum[31];

    if (tid == 0) {
        g_part[blockIdx.x] = block_total;
        __threadfence();
        atomicAdd(&g_flag, 1);
        while (atomicAdd(&g_flag, 0) < (int)gridDim.x) { }
        __threadfence();
        int o = 0;
        for (int b = 0; b < (int)blockIdx.x; b++) o += g_part[b];
        s_off = o;
        if (blockIdx.x == gridDim.x - 1) g_rowptr[n] = o + block_total;
    }
    __syncthreads();
    int run = s_off + local_excl;
    if (i < n) {
        g_rowptr[i] = run;
        g_cursor[i] = run;
        g_dinv[i]   = rsqrtf((float)c + 1.0f);
    }
}

// ---------------- pipelined GEMM accumulate core ----------------
// Register double-buffered: W/A for step k4+4 load while k4 computes.
template<int BN, int RPT>
__device__ __forceinline__ void gemm_acc_pipe(
    const float* __restrict__ A, const float* __restrict__ W,
    int row0, int col0, unsigned long long (&acc)[RPT][2])
{
    F4U2 w[4], a[RPT];
    #pragma unroll
    for (int kk = 0; kk < 4; kk++)
        w[kk].f = *(const float4*)&W[kk * BN + col0];
    #pragma unroll
    for (int r = 0; r < RPT; r++)
        a[r].f = *(const float4*)&A[(size_t)(row0 + r) * 128];

    #pragma unroll
    for (int k4 = 0; k4 < 128; k4 += 4) {
        F4U2 wn[4], an[RPT];
        if (k4 + 4 < 128) {
            #pragma unroll
            for (int kk = 0; kk < 4; kk++)
                wn[kk].f = *(const float4*)&W[(k4 + 4 + kk) * BN + col0];
            #pragma unroll
            for (int r = 0; r < RPT; r++)
                an[r].f = *(const float4*)&A[(size_t)(row0 + r) * 128 + k4 + 4];
        }
        #pragma unroll
        for (int r = 0; r < RPT; r++) {
            unsigned long long ax = dup2(a[r].s.x), ay = dup2(a[r].s.y),
                               az = dup2(a[r].s.z), aw = dup2(a[r].s.w);
            fma2(acc[r][0], ax, w[0].u.lo); fma2(acc[r][1], ax, w[0].u.hi);
            fma2(acc[r][0], ay, w[1].u.lo); fma2(acc[r][1], ay, w[1].u.hi);
            fma2(acc[r][0], az, w[2].u.lo); fma2(acc[r][1], az, w[2].u.hi);
            fma2(acc[r][0], aw, w[3].u.lo); fma2(acc[r][1], aw, w[3].u.hi);
        }
        #pragma unroll
        for (int kk = 0; kk < 4; kk++) w[kk] = wn[kk];
        #pragma unroll
        for (int r = 0; r < RPT; r++) a[r] = an[r];
    }
}

// ---------------- GEMM body (TN=4; BN=128: CT=32 warp-uniform A) ----------------
template<int BN, int ACT>
__device__ __forceinline__ void gemm_body(
    const float* __restrict__ A, const float* __restrict__ W,
    const float* __restrict__ bias, float* __restrict__ C,
    int nrows, int bid)
{
    constexpr int TN  = 4;
    constexpr int CT  = BN / TN;
    constexpr int RT  = 256 / CT;
    constexpr int BM  = 32;
    constexpr int RPT = BM / RT;
    const int tid  = threadIdx.x;
    const int tc   = tid % CT;
    const int tr   = tid / CT;
    const int row0 = bid * BM + tr * RPT;
    const int col0 = tc * TN;
    if (row0 >= nrows) return;

    unsigned long long acc[RPT][2];
    #pragma unroll
    for (int r = 0; r < RPT; r++) { acc[r][0] = 0ull; acc[r][1] = 0ull; }

    gemm_acc_pipe<BN, RPT>(A, W, row0, col0, acc);

    #pragma unroll
    for (int r = 0; r < RPT; r++) {
        F4U2 o;
        o.u.lo = acc[r][0]; o.u.hi = acc[r][1];
        float v[4] = {o.s.x, o.s.y, o.s.z, o.s.w};
        #pragma unroll
        for (int c = 0; c < TN; c++) {
            float t = v[c];
            if (bias) t += bias[col0 + c];
            if (ACT == 1) t = fmaxf(t, 0.0f);
            if (ACT == 2) t = gelu_f(t);
            v[c] = t;
        }
        o.s.x = v[0]; o.s.y = v[1]; o.s.z = v[2]; o.s.w = v[3];
        *(float4*)&C[(size_t)(row0 + r) * BN + col0] = o.f;
    }
}

template<int BN, int ACT>
__global__ void __launch_bounds__(256) gemm_k(
    const float* __restrict__ A, const float* __restrict__ W,
    const float* __restrict__ bias, float* __restrict__ C, int nrows)
{
    gemm_body<BN, ACT>(A, W, bias, C, nrows, blockIdx.x);
}

// fused: blocks [0, gb) do GEMM1 (feat@W_gcn); rest do CSR fill
__global__ void __launch_bounds__(256) gemm1_fill_k(
    const float* __restrict__ A, const float* __restrict__ W,
    float* __restrict__ C, int nrows, int gb, int E)
{
    if ((int)blockIdx.x < gb) {
        gemm_body<128, 0>(A, W, nullptr, C, nrows, blockIdx.x);
    } else {
        int e = (blockIdx.x - gb) * 256 + threadIdx.x;
        if (e >= E) return;
        int d = g_dst[e];
        int slot = atomicAdd(&g_cursor[d], 1);
        g_csrc[slot] = g_src[e];
    }
}

// ---------------- GCN gather (scalar, 2-edge unroll, MLP=8) ----------------
__global__ void gcn_gather_k(const float* __restrict__ bias, int n) {
    int node = blockIdx.x * (blockDim.x >> 5) + (threadIdx.x >> 5);
    if (node >= n) return;
    int lane = threadIdx.x & 31;
    int beg = g_rowptr[node], end = g_rowptr[node + 1];
    float dd = g_dinv[node];
    const float* xd = g_x + (size_t)node * HID;
    float sl = dd * dd;
    float a0 = xd[lane] * sl;
    float a1 = xd[lane + 32] * sl;
    float a2 = xd[lane + 64] * sl;
    float a3 = xd[lane + 96] * sl;

    int e = beg;
    for (; e + 1 < end; e += 2) {
        int s0 = g_csrc[e], s1 = g_csrc[e + 1];
        float c0 = g_dinv[s0] * dd, c1 = g_dinv[s1] * dd;
        const float* x0 = g_x + (size_t)s0 * HID;
        const float* x1 = g_x + (size_t)s1 * HID;
        float v00 = x0[lane],      v01 = x1[lane];
        float v10 = x0[lane + 32], v11 = x1[lane + 32];
        float v20 = x0[lane + 64], v21 = x1[lane + 64];
        float v30 = x0[lane + 96], v31 = x1[lane + 96];
        a0 = fmaf(v00, c0, a0); a0 = fmaf(v01, c1, a0);
        a1 = fmaf(v10, c0, a1); a1 = fmaf(v11, c1, a1);
        a2 = fmaf(v20, c0, a2); a2 = fmaf(v21, c1, a2);
        a3 = fmaf(v30, c0, a3); a3 = fmaf(v31, c1, a3);
    }
    if (e < end) {
        int s0 = g_csrc[e];
        float c0 = g_dinv[s0] * dd;
        const float* x0 = g_x + (size_t)s0 * HID;
        a0 = fmaf(x0[lane],      c0, a0);
        a1 = fmaf(x0[lane + 32], c0, a1);
        a2 = fmaf(x0[lane + 64], c0, a2);
        a3 = fmaf(x0[lane + 96], c0, a3);
    }
    float* out = g_h1 + (size_t)node * HID;
    out[lane]      = fmaxf(a0 + bias[lane],      0.0f);
    out[lane + 32] = fmaxf(a1 + bias[lane + 32], 0.0f);
    out[lane + 64] = fmaxf(a2 + bias[lane + 64], 0.0f);
    out[lane + 96] = fmaxf(a3 + bias[lane + 96], 0.0f);
}

// ---------------- SAGE gather ----------------
__global__ void sage_gather_k(int n) {
    int node = blockIdx.x * (blockDim.x >> 5) + (threadIdx.x >> 5);
    if (node >= n) return;
    int lane = threadIdx.x & 31;
    int beg = g_rowptr[node], end = g_rowptr[node + 1];
    float a0 = 0.f, a1 = 0.f, a2 = 0.f, a3 = 0.f;
    int e = beg;
    for (; e + 1 < end; e += 2) {
        int s0 = g_csrc[e], s1 = g_csrc[e + 1];
        const float* x0 = g_h1 + (size_t)s0 * HID;
        const float* x1 = g_h1 + (size_t)s1 * HID;
        a0 += x0[lane];      a0 += x1[lane];
        a1 += x0[lane + 32]; a1 += x1[lane + 32];
        a2 += x0[lane + 64]; a2 += x1[lane + 64];
        a3 += x0[lane + 96]; a3 += x1[lane + 96];
    }
    if (e < end) {
        int s0 = g_csrc[e];
        const float* x0 = g_h1 + (size_t)s0 * HID;
        a0 += x0[lane]; a1 += x0[lane + 32]; a2 += x0[lane + 64]; a3 += x0[lane + 96];
    }
    int deg = end - beg;
    float inv = 1.0f / (float)max(deg, 1);
    float* out = g_ns + (size_t)node * HID;
    out[lane]      = a0 * inv;
    out[lane + 32] = a1 * inv;
    out[lane + 64] = a2 * inv;
    out[lane + 96] = a3 * inv;
}

// fused SAGE GEMM + value head
__global__ void __launch_bounds__(256) gemm2_k(
    const float* __restrict__ A1, const float* __restrict__ W1,
    const float* __restrict__ A2, const float* __restrict__ W2,
    const float* __restrict__ bias,
    float* __restrict__ C, int nrows,
    const float* __restrict__ Wv, const float* __restrict__ bv,
    float* __restrict__ values_out)
{
    constexpr int BN = 128, TN = 4, CT = 32, RPT = 4, BM = 32;
    const int tid  = threadIdx.x;
    const int tc   = tid % CT;
    const int tr   = tid / CT;
    const int row0 = blockIdx.x * BM + tr * RPT;
    const int col0 = tc * TN;
    if (row0 >= nrows) return;

    unsigned long long acc[RPT][2];
    #pragma unroll
    for (int r = 0; r < RPT; r++) { acc[r][0] = 0ull; acc[r][1] = 0ull; }

    gemm_acc_pipe<BN, RPT>(A1, W1, row0, col0, acc);
    gemm_acc_pipe<BN, RPT>(A2, W2, row0, col0, acc);

    float4 wv = *(const float4*)&Wv[col0];
    float bv0 = bv[0];
    #pragma unroll
    for (int r = 0; r < RPT; r++) {
        F4U2 o;
        o.u.lo = acc[r][0]; o.u.hi = acc[r][1];
        o.s.x = fmaxf(o.s.x + bias[col0 + 0], 0.0f);
        o.s.y = fmaxf(o.s.y + bias[col0 + 1], 0.0f);
        o.s.z = fmaxf(o.s.z + bias[col0 + 2], 0.0f);
        o.s.w = fmaxf(o.s.w + bias[col0 + 3], 0.0f);
        *(float4*)&C[(size_t)(row0 + r) * BN + col0] = o.f;
        float p = fmaf(o.s.x, wv.x, fmaf(o.s.y, wv.y,
                  fmaf(o.s.z, wv.z, o.s.w * wv.w)));
        #pragma unroll
        for (int off = 16; off > 0; off >>= 1)
            p += __shfl_xor_sync(0xFFFFFFFFu, p, off);
        if (tc == 0) values_out[row0 + r] = p + bv0;
    }
}

// ---------------- launch ----------------
extern "C" void kernel_launch(void* const* d_in, const int* in_sizes, int n_in,
                              void* d_out, int out_size)
{
    const float* feat     = (const float*)d_in[0];
    const void*  ei       = d_in[1];
    const float* W_gcn    = (const float*)d_in[2];
    const float* b_gcn    = (const float*)d_in[3];
    const float* W_sage_l = (const float*)d_in[4];
    const float* b_sage_l = (const float*)d_in[5];
    const float* W_sage_r = (const float*)d_in[6];
    const float* W1       = (const float*)d_in[7];
    const float* b1       = (const float*)d_in[8];
    const float* W2       = (const float*)d_in[9];
    const float* b2       = (const float*)d_in[10];
    const float* W3       = (const float*)d_in[11];
    const float* b3       = (const float*)d_in[12];
    const float* Wv       = (const float*)d_in[13];
    const float* bv       = (const float*)d_in[14];

    const int N = in_sizes[0] / HID;   // 20000
    const int E = in_sizes[1] / 2;     // 640000

    float* means_out  = (float*)d_out;            // [N, 64]
    float* values_out = (float*)d_out + (size_t)N * 64;

    float *p_x, *p_h1, *p_ns, *p_h2;
    cudaGetSymbolAddress((void**)&p_x,  g_x);
    cudaGetSymbolAddress((void**)&p_h1, g_h1);
    cudaGetSymbolAddress((void**)&p_ns, g_ns);
    cudaGetSymbolAddress((void**)&p_h2, g_h2);

    const int TB = 256;
    const int e_blocks    = (E + TB - 1) / TB;       // 2500
    const int nw_blocks   = (N * 32 + TB - 1) / TB;  // warp per node
    const int scan_blocks = (N + 1023) / 1024;       // 20
    const int gemm_blocks = (N + 31) / 32;           // 625

    init_k<<<80, TB>>>((const int*)ei, N);
    convert_count_k<<<e_blocks, TB>>>(ei, E);
    scan_fused_k<<<scan_blocks, 1024>>>(N);
    gemm1_fill_k<<<gemm_blocks + e_blocks, TB>>>(feat, W_gcn, p_x, N,
                                                 gemm_blocks, E);
    gcn_gather_k<<<nw_blocks, TB>>>(b_gcn, N);
    sage_gather_k<<<nw_blocks, TB>>>(N);
    gemm2_k<<<gemm_blocks, TB>>>(p_ns, W_sage_l, p_h1, W_sage_r, b_sage_l,
                                 p_h2, N, Wv, bv, values_out);
    gemm_k<128, 2><<<gemm_blocks, TB>>>(p_h2, W1, b1, p_x, N);
    gemm_k<128, 2><<<gemm_blocks, TB>>>(p_x, W2, b2, p_ns, N);
    gemm_k<64, 0><<<gemm_blocks, TB>>>(p_ns, W3, b3, means_out, N);
}

// round 10
// speedup vs baseline: 1.2732x; 1.2600x over previous
#include <cuda_runtime.h>
#include <math.h>

#define NN 20000
#define EE 640000
#define HID 128

// ---------------- scratch (device globals; no allocation) ----------------
__device__ int   g_is64;
__device__ int   g_flag;
__device__ int   g_src[EE];
__device__ int   g_dst[EE];
__device__ int   g_csrc[EE];
__device__ int   g_icnt[NN];
__device__ int   g_rowptr[NN + 1];
__device__ int   g_cursor[NN];
__device__ int   g_part[64];
__device__ float g_dinv[NN];
__device__ float g_x  [NN * HID];
__device__ float g_h1 [NN * HID];
__device__ float g_ns [NN * HID];
__device__ float g_h2 [NN * HID];

// ---------------- small helpers ----------------
__device__ __forceinline__ float gelu_f(float x) {
    return 0.5f * x * (1.0f + erff(x * 0.70710678118654752440f));
}
__device__ __forceinline__ void fma2(unsigned long long& acc,
                                     unsigned long long a, unsigned long long b) {
    asm("fma.rn.f32x2 %0, %1, %2, %0;" : "+l"(acc) : "l"(a), "l"(b));
}
__device__ __forceinline__ unsigned long long dup2(float a) {
    unsigned long long r;
    asm("mov.b64 %0, {%1, %1};" : "=l"(r) : "f"(a));
    return r;
}
union F4U2 {
    float4 f;
    struct { unsigned long long lo, hi; } u;
    struct { float x, y, z, w; } s;
};

// ---------------- init ----------------
__global__ void init_k(const int* __restrict__ ei_words, int n) {
    int idx = blockIdx.x * blockDim.x + threadIdx.x;
    int stride = gridDim.x * blockDim.x;
    for (int i = idx; i < n; i += stride) g_icnt[i] = 0;
    if (idx == 0) g_flag = 0;
    if (blockIdx.x == 0 && threadIdx.x < 64) {
        int hi = ei_words[2 * threadIdx.x + 1];
        __shared__ unsigned s[2];
        unsigned b = __ballot_sync(0xFFFFFFFFu, hi != 0);
        if ((threadIdx.x & 31) == 0) s[threadIdx.x >> 5] = b;
        __syncthreads();
        if (threadIdx.x == 0) g_is64 = ((s[0] | s[1]) == 0u) ? 1 : 0;
    }
}

__global__ void convert_count_k(const void* __restrict__ ei, int E) {
    int e = blockIdx.x * blockDim.x + threadIdx.x;
    if (e >= E) return;
    int s, d;
    if (g_is64) {
        const long long* p = (const long long*)ei;
        s = (int)p[e]; d = (int)p[E + e];
    } else {
        const int* p = (const int*)ei;
        s = p[e]; d = p[E + e];
    }
    g_src[e] = s;
    g_dst[e] = d;
    atomicAdd(&g_icnt[d], 1);
}

// ---------------- single-launch scan ----------------
__global__ void __launch_bounds__(1024) scan_fused_k(int n) {
    __shared__ int wsum[32];
    __shared__ int s_off;
    int tid = threadIdx.x, lane = tid & 31, wid = tid >> 5;
    int i = blockIdx.x * 1024 + tid;
    int c = (i < n) ? g_icnt[i] : 0;
    int incl = c;
    #pragma unroll
    for (int off = 1; off < 32; off <<= 1) {
        int u = __shfl_up_sync(0xFFFFFFFFu, incl, off);
        if (lane >= off) incl += u;
    }
    if (lane == 31) wsum[wid] = incl;
    __syncthreads();
    if (wid == 0) {
        int t = wsum[lane];
        #pragma unroll
        for (int off = 1; off < 32; off <<= 1) {
            int u = __shfl_up_sync(0xFFFFFFFFu, t, off);
            if (lane >= off) t += u;
        }
        wsum[lane] = t;
    }
    __syncthreads();
    int warp_off = (wid == 0) ? 0 : wsum[wid - 1];
    int local_excl = warp_off + incl - c;
    int block_total = wsum[31];

    if (tid == 0) {
        g_part[blockIdx.x] = block_total;
        __threadfence();
        atomicAdd(&g_flag, 1);
        while (atomicAdd(&g_flag, 0) < (int)gridDim.x) { }
        __threadfence();
        int o = 0;
        for (int b = 0; b < (int)blockIdx.x; b++) o += g_part[b];
        s_off = o;
        if (blockIdx.x == gridDim.x - 1) g_rowptr[n] = o + block_total;
    }
    __syncthreads();
    int run = s_off + local_excl;
    if (i < n) {
        g_rowptr[i] = run;
        g_cursor[i] = run;
        g_dinv[i]   = rsqrtf((float)c + 1.0f);
    }
}

// ---------------- smem GEMM ----------------
// BM=64 rows/block, 256 threads. A tile (64x128) + full W (128xBN) in smem.
// Inner loop pure LDS+FMA2; FMA-bound by construction.
#define GBM 64

// stage helpers (all 256 threads; callers sync after)
__device__ __forceinline__ void stage_A(const float* __restrict__ A,
                                        float* As, int row_base, int nrows) {
    int tid = threadIdx.x;
    #pragma unroll
    for (int i = tid; i < GBM * 32; i += 256) {
        int r = i >> 5, c = i & 31;
        float4 v = make_float4(0.f, 0.f, 0.f, 0.f);
        if (row_base + r < nrows)
            v = ((const float4*)A)[(size_t)(row_base + r) * 32 + c];
        ((float4*)As)[i] = v;
    }
}
template<int BN>
__device__ __forceinline__ void stage_W(const float* __restrict__ W, float* Ws) {
    int tid = threadIdx.x;
    #pragma unroll
    for (int i = tid; i < 128 * BN / 4; i += 256)
        ((float4*)Ws)[i] = ((const float4*)W)[i];
}

// accumulate from smem tiles
template<int BN, int RPT>
__device__ __forceinline__ void gemm_acc_smem(
    const float* As, const float* Ws,
    int rl0, int col0, unsigned long long (&acc)[RPT][2])
{
    #pragma unroll 4
    for (int k4 = 0; k4 < 128; k4 += 4) {
        F4U2 w0, w1, w2, w3;
        w0.f = *(const float4*)&Ws[(k4 + 0) * BN + col0];
        w1.f = *(const float4*)&Ws[(k4 + 1) * BN + col0];
        w2.f = *(const float4*)&Ws[(k4 + 2) * BN + col0];
        w3.f = *(const float4*)&Ws[(k4 + 3) * BN + col0];
        #pragma unroll
        for (int r = 0; r < RPT; r++) {
            F4U2 a;
            a.f = *(const float4*)&As[(rl0 + r) * 128 + k4];
            unsigned long long ax = dup2(a.s.x), ay = dup2(a.s.y),
                               az = dup2(a.s.z), aw = dup2(a.s.w);
            fma2(acc[r][0], ax, w0.u.lo); fma2(acc[r][1], ax, w0.u.hi);
            fma2(acc[r][0], ay, w1.u.lo); fma2(acc[r][1], ay, w1.u.hi);
            fma2(acc[r][0], az, w2.u.lo); fma2(acc[r][1], az, w2.u.hi);
            fma2(acc[r][0], aw, w3.u.lo); fma2(acc[r][1], aw, w3.u.hi);
        }
    }
}

template<int BN, int ACT>
__device__ __forceinline__ void gemm_body_smem(
    const float* __restrict__ A, const float* __restrict__ W,
    const float* __restrict__ bias, float* __restrict__ C,
    int nrows, int bid, float* sm)
{
    constexpr int CT  = BN / 4;
    constexpr int RT  = 256 / CT;
    constexpr int RPT = GBM / RT;
    float* As = sm;
    float* Ws = sm + GBM * 128;

    int row_base = bid * GBM;
    stage_A(A, As, row_base, nrows);
    stage_W<BN>(W, Ws);
    __syncthreads();

    const int tid  = threadIdx.x;
    const int tc   = tid % CT;
    const int tr   = tid / CT;
    const int rl0  = tr * RPT;
    const int col0 = tc * 4;

    unsigned long long acc[RPT][2];
    #pragma unroll
    for (int r = 0; r < RPT; r++) { acc[r][0] = 0ull; acc[r][1] = 0ull; }

    gemm_acc_smem<BN, RPT>(As, Ws, rl0, col0, acc);

    #pragma unroll
    for (int r = 0; r < RPT; r++) {
        if (row_base + rl0 + r >= nrows) break;
        F4U2 o;
        o.u.lo = acc[r][0]; o.u.hi = acc[r][1];
        float v[4] = {o.s.x, o.s.y, o.s.z, o.s.w};
        #pragma unroll
        for (int c = 0; c < 4; c++) {
            float t = v[c];
            if (bias) t += bias[col0 + c];
            if (ACT == 1) t = fmaxf(t, 0.0f);
            if (ACT == 2) t = gelu_f(t);
            v[c] = t;
        }
        o.s.x = v[0]; o.s.y = v[1]; o.s.z = v[2]; o.s.w = v[3];
        *(float4*)&C[(size_t)(row_base + rl0 + r) * BN + col0] = o.f;
    }
}

template<int BN, int ACT>
__global__ void __launch_bounds__(256) gemm_k(
    const float* __restrict__ A, const float* __restrict__ W,
    const float* __restrict__ bias, float* __restrict__ C, int nrows)
{
    extern __shared__ float sm[];
    gemm_body_smem<BN, ACT>(A, W, bias, C, nrows, blockIdx.x, sm);
}

// fused: blocks [0, gb) do GEMM1 (feat@W_gcn); rest do CSR fill
__global__ void __launch_bounds__(256) gemm1_fill_k(
    const float* __restrict__ A, const float* __restrict__ W,
    float* __restrict__ C, int nrows, int gb, int E)
{
    extern __shared__ float sm[];
    if ((int)blockIdx.x < gb) {
        gemm_body_smem<128, 0>(A, W, nullptr, C, nrows, blockIdx.x, sm);
    } else {
        int e = (blockIdx.x - gb) * 256 + threadIdx.x;
        if (e >= E) return;
        int d = g_dst[e];
        int slot = atomicAdd(&g_cursor[d], 1);
        g_csrc[slot] = g_src[e];
    }
}

// fused SAGE GEMM (two staged passes) + value head
__global__ void __launch_bounds__(256) gemm2_k(
    const float* __restrict__ A1, const float* __restrict__ W1,
    const float* __restrict__ A2, const float* __restrict__ W2,
    const float* __restrict__ bias,
    float* __restrict__ C, int nrows,
    const float* __restrict__ Wv, const float* __restrict__ bv,
    float* __restrict__ values_out)
{
    constexpr int BN = 128, CT = 32, RPT = GBM / (256 / CT);  // RPT=8
    extern __shared__ float sm[];
    float* As = sm;
    float* Ws = sm + GBM * 128;

    int row_base = blockIdx.x * GBM;
    const int tid  = threadIdx.x;
    const int tc   = tid % CT;
    const int tr   = tid / CT;
    const int rl0  = tr * RPT;
    const int col0 = tc * 4;

    unsigned long long acc[RPT][2];
    #pragma unroll
    for (int r = 0; r < RPT; r++) { acc[r][0] = 0ull; acc[r][1] = 0ull; }

    // pass 1: A1@W1
    stage_A(A1, As, row_base, nrows);
    stage_W<BN>(W1, Ws);
    __syncthreads();
    gemm_acc_smem<BN, RPT>(As, Ws, rl0, col0, acc);
    __syncthreads();
    // pass 2: A2@W2 (restage same buffers)
    stage_A(A2, As, row_base, nrows);
    stage_W<BN>(W2, Ws);
    __syncthreads();
    gemm_acc_smem<BN, RPT>(As, Ws, rl0, col0, acc);

    float4 wv = *(const float4*)&Wv[col0];
    float bv0 = bv[0];
    #pragma unroll
    for (int r = 0; r < RPT; r++) {
        int row = row_base + rl0 + r;
        F4U2 o;
        o.u.lo = acc[r][0]; o.u.hi = acc[r][1];
        o.s.x = fmaxf(o.s.x + bias[col0 + 0], 0.0f);
        o.s.y = fmaxf(o.s.y + bias[col0 + 1], 0.0f);
        o.s.z = fmaxf(o.s.z + bias[col0 + 2], 0.0f);
        o.s.w = fmaxf(o.s.w + bias[col0 + 3], 0.0f);
        float p = fmaf(o.s.x, wv.x, fmaf(o.s.y, wv.y,
                  fmaf(o.s.z, wv.z, o.s.w * wv.w)));
        #pragma unroll
        for (int off = 16; off > 0; off >>= 1)
            p += __shfl_xor_sync(0xFFFFFFFFu, p, off);
        if (row < nrows) {
            *(float4*)&C[(size_t)row * BN + col0] = o.f;
            if (tc == 0) values_out[row] = p + bv0;
        }
    }
}

// ---------------- GCN gather (scalar, 2-edge unroll, MLP=8) ----------------
__global__ void gcn_gather_k(const float* __restrict__ bias, int n) {
    int node = blockIdx.x * (blockDim.x >> 5) + (threadIdx.x >> 5);
    if (node >= n) return;
    int lane = threadIdx.x & 31;
    int beg = g_rowptr[node], end = g_rowptr[node + 1];
    float dd = g_dinv[node];
    const float* xd = g_x + (size_t)node * HID;
    float sl = dd * dd;
    float a0 = xd[lane] * sl;
    float a1 = xd[lane + 32] * sl;
    float a2 = xd[lane + 64] * sl;
    float a3 = xd[lane + 96] * sl;

    int e = beg;
    for (; e + 1 < end; e += 2) {
        int s0 = g_csrc[e], s1 = g_csrc[e + 1];
        float c0 = g_dinv[s0] * dd, c1 = g_dinv[s1] * dd;
        const float* x0 = g_x + (size_t)s0 * HID;
        const float* x1 = g_x + (size_t)s1 * HID;
        float v00 = x0[lane],      v01 = x1[lane];
        float v10 = x0[lane + 32], v11 = x1[lane + 32];
        float v20 = x0[lane + 64], v21 = x1[lane + 64];
        float v30 = x0[lane + 96], v31 = x1[lane + 96];
        a0 = fmaf(v00, c0, a0); a0 = fmaf(v01, c1, a0);
        a1 = fmaf(v10, c0, a1); a1 = fmaf(v11, c1, a1);
        a2 = fmaf(v20, c0, a2); a2 = fmaf(v21, c1, a2);
        a3 = fmaf(v30, c0, a3); a3 = fmaf(v31, c1, a3);
    }
    if (e < end) {
        int s0 = g_csrc[e];
        float c0 = g_dinv[s0] * dd;
        const float* x0 = g_x + (size_t)s0 * HID;
        a0 = fmaf(x0[lane],      c0, a0);
        a1 = fmaf(x0[lane + 32], c0, a1);
        a2 = fmaf(x0[lane + 64], c0, a2);
        a3 = fmaf(x0[lane + 96], c0, a3);
    }
    float* out = g_h1 + (size_t)node * HID;
    out[lane]      = fmaxf(a0 + bias[lane],      0.0f);
    out[lane + 32] = fmaxf(a1 + bias[lane + 32], 0.0f);
    out[lane + 64] = fmaxf(a2 + bias[lane + 64], 0.0f);
    out[lane + 96] = fmaxf(a3 + bias[lane + 96], 0.0f);
}

// ---------------- SAGE gather ----------------
__global__ void sage_gather_k(int n) {
    int node = blockIdx.x * (blockDim.x >> 5) + (threadIdx.x >> 5);
    if (node >= n) return;
    int lane = threadIdx.x & 31;
    int beg = g_rowptr[node], end = g_rowptr[node + 1];
    float a0 = 0.f, a1 = 0.f, a2 = 0.f, a3 = 0.f;
    int e = beg;
    for (; e + 1 < end; e += 2) {
        int s0 = g_csrc[e], s1 = g_csrc[e + 1];
        const float* x0 = g_h1 + (size_t)s0 * HID;
        const float* x1 = g_h1 + (size_t)s1 * HID;
        a0 += x0[lane];      a0 += x1[lane];
        a1 += x0[lane + 32]; a1 += x1[lane + 32];
        a2 += x0[lane + 64]; a2 += x1[lane + 64];
        a3 += x0[lane + 96]; a3 += x1[lane + 96];
    }
    if (e < end) {
        int s0 = g_csrc[e];
        const float* x0 = g_h1 + (size_t)s0 * HID;
        a0 += x0[lane]; a1 += x0[lane + 32]; a2 += x0[lane + 64]; a3 += x0[lane + 96];
    }
    int deg = end - beg;
    float inv = 1.0f / (float)max(deg, 1);
    float* out = g_ns + (size_t)node * HID;
    out[lane]      = a0 * inv;
    out[lane + 32] = a1 * inv;
    out[lane + 64] = a2 * inv;
    out[lane + 96] = a3 * inv;
}

// ---------------- launch ----------------
extern "C" void kernel_launch(void* const* d_in, const int* in_sizes, int n_in,
                              void* d_out, int out_size)
{
    const float* feat     = (const float*)d_in[0];
    const void*  ei       = d_in[1];
    const float* W_gcn    = (const float*)d_in[2];
    const float* b_gcn    = (const float*)d_in[3];
    const float* W_sage_l = (const float*)d_in[4];
    const float* b_sage_l = (const float*)d_in[5];
    const float* W_sage_r = (const float*)d_in[6];
    const float* W1       = (const float*)d_in[7];
    const float* b1       = (const float*)d_in[8];
    const float* W2       = (const float*)d_in[9];
    const float* b2       = (const float*)d_in[10];
    const float* W3       = (const float*)d_in[11];
    const float* b3       = (const float*)d_in[12];
    const float* Wv       = (const float*)d_in[13];
    const float* bv       = (const float*)d_in[14];

    const int N = in_sizes[0] / HID;   // 20000
    const int E = in_sizes[1] / 2;     // 640000

    float* means_out  = (float*)d_out;            // [N, 64]
    float* values_out = (float*)d_out + (size_t)N * 64;

    float *p_x, *p_h1, *p_ns, *p_h2;
    cudaGetSymbolAddress((void**)&p_x,  g_x);
    cudaGetSymbolAddress((void**)&p_h1, g_h1);
    cudaGetSymbolAddress((void**)&p_ns, g_ns);
    cudaGetSymbolAddress((void**)&p_h2, g_h2);

    const int TB = 256;
    const int e_blocks    = (E + TB - 1) / TB;        // 2500
    const int nw_blocks   = (N * 32 + TB - 1) / TB;   // warp per node
    const int scan_blocks = (N + 1023) / 1024;        // 20
    const int gemm_blocks = (N + GBM - 1) / GBM;      // 313

    // dynamic smem sizes (>48KB needs opt-in; host attr set, capture-safe)
    const int SM128 = (GBM * 128 + 128 * 128) * 4;    // 96 KB
    const int SM64  = (GBM * 128 + 128 * 64)  * 4;    // 64 KB
    static int attrs_set = 0;
    if (!attrs_set) {
        cudaFuncSetAttribute(gemm1_fill_k,
            cudaFuncAttributeMaxDynamicSharedMemorySize, SM128);
        cudaFuncSetAttribute(gemm2_k,
            cudaFuncAttributeMaxDynamicSharedMemorySize, SM128);
        cudaFuncSetAttribute(gemm_k<128, 2>,
            cudaFuncAttributeMaxDynamicSharedMemorySize, SM128);
        cudaFuncSetAttribute(gemm_k<64, 0>,
            cudaFuncAttributeMaxDynamicSharedMemorySize, SM64);
        attrs_set = 1;
    }

    init_k<<<80, TB>>>((const int*)ei, N);
    convert_count_k<<<e_blocks, TB>>>(ei, E);
    scan_fused_k<<<scan_blocks, 1024>>>(N);
    gemm1_fill_k<<<gemm_blocks + e_blocks, TB, SM128>>>(feat, W_gcn, p_x, N,
                                                        gemm_blocks, E);
    gcn_gather_k<<<nw_blocks, TB>>>(b_gcn, N);
    sage_gather_k<<<nw_blocks, TB>>>(N);
    gemm2_k<<<gemm_blocks, TB, SM128>>>(p_ns, W_sage_l, p_h1, W_sage_r,
                                        b_sage_l, p_h2, N, Wv, bv, values_out);
    gemm_k<128, 2><<<gemm_blocks, TB, SM128>>>(p_h2, W1, b1, p_x, N);
    gemm_k<128, 2><<<gemm_blocks, TB, SM128>>>(p_x, W2, b2, p_ns, N);
    gemm_k<64, 0><<<gemm_blocks, TB, SM64>>>(p_ns, W3, b3, means_out, N);
}

// round 11
// speedup vs baseline: 1.3024x; 1.0229x over previous
#include <cuda_runtime.h>
#include <math.h>

#define NN 20000
#define EE 640000
#define HID 128

// ---------------- scratch (device globals; no allocation) ----------------
__device__ int   g_is64;
__device__ int   g_flag;
__device__ int   g_src[EE];
__device__ int   g_dst[EE];
__device__ int   g_csrc[EE];
__device__ int   g_icnt[NN];
__device__ int   g_rowptr[NN + 1];
__device__ int   g_cursor[NN];
__device__ int   g_part[64];
__device__ float g_dinv[NN];
__device__ float g_x  [NN * HID];
__device__ float g_h1 [NN * HID];
__device__ float g_ns [NN * HID];

// ---------------- small helpers ----------------
__device__ __forceinline__ float gelu_f(float x) {
    return 0.5f * x * (1.0f + erff(x * 0.70710678118654752440f));
}
__device__ __forceinline__ void fma2(unsigned long long& acc,
                                     unsigned long long a, unsigned long long b) {
    asm("fma.rn.f32x2 %0, %1, %2, %0;" : "+l"(acc) : "l"(a), "l"(b));
}
__device__ __forceinline__ unsigned long long dup2(float a) {
    unsigned long long r;
    asm("mov.b64 %0, {%1, %1};" : "=l"(r) : "f"(a));
    return r;
}
union F4U2 {
    float4 f;
    struct { unsigned long long lo, hi; } u;
    struct { float x, y, z, w; } s;
};

// ---------------- init ----------------
__global__ void init_k(const int* __restrict__ ei_words, int n) {
    int idx = blockIdx.x * blockDim.x + threadIdx.x;
    int stride = gridDim.x * blockDim.x;
    for (int i = idx; i < n; i += stride) g_icnt[i] = 0;
    if (idx == 0) g_flag = 0;
    if (blockIdx.x == 0 && threadIdx.x < 64) {
        int hi = ei_words[2 * threadIdx.x + 1];
        __shared__ unsigned s[2];
        unsigned b = __ballot_sync(0xFFFFFFFFu, hi != 0);
        if ((threadIdx.x & 31) == 0) s[threadIdx.x >> 5] = b;
        __syncthreads();
        if (threadIdx.x == 0) g_is64 = ((s[0] | s[1]) == 0u) ? 1 : 0;
    }
}

__global__ void convert_count_k(const void* __restrict__ ei, int E) {
    int e = blockIdx.x * blockDim.x + threadIdx.x;
    if (e >= E) return;
    int s, d;
    if (g_is64) {
        const long long* p = (const long long*)ei;
        s = (int)p[e]; d = (int)p[E + e];
    } else {
        const int* p = (const int*)ei;
        s = p[e]; d = p[E + e];
    }
    g_src[e] = s;
    g_dst[e] = d;
    atomicAdd(&g_icnt[d], 1);
}

// ---------------- single-launch scan ----------------
__global__ void __launch_bounds__(1024) scan_fused_k(int n) {
    __shared__ int wsum[32];
    __shared__ int s_off;
    int tid = threadIdx.x, lane = tid & 31, wid = tid >> 5;
    int i = blockIdx.x * 1024 + tid;
    int c = (i < n) ? g_icnt[i] : 0;
    int incl = c;
    #pragma unroll
    for (int off = 1; off < 32; off <<= 1) {
        int u = __shfl_up_sync(0xFFFFFFFFu, incl, off);
        if (lane >= off) incl += u;
    }
    if (lane == 31) wsum[wid] = incl;
    __syncthreads();
    if (wid == 0) {
        int t = wsum[lane];
        #pragma unroll
        for (int off = 1; off < 32; off <<= 1) {
            int u = __shfl_up_sync(0xFFFFFFFFu, t, off);
            if (lane >= off) t += u;
        }
        wsum[lane] = t;
    }
    __syncthreads();
    int warp_off = (wid == 0) ? 0 : wsum[wid - 1];
    int local_excl = warp_off + incl - c;
    int block_total = wsum[31];

    if (tid == 0) {
        g_part[blockIdx.x] = block_total;
        __threadfence();
        atomicAdd(&g_flag, 1);
        while (atomicAdd(&g_flag, 0) < (int)gridDim.x) { }
        __threadfence();
        int o = 0;
        for (int b = 0; b < (int)blockIdx.x; b++) o += g_part[b];
        s_off = o;
        if (blockIdx.x == gridDim.x - 1) g_rowptr[n] = o + block_total;
    }
    __syncthreads();
    int run = s_off + local_excl;
    if (i < n) {
        g_rowptr[i] = run;
        g_cursor[i] = run;
        g_dinv[i]   = rsqrtf((float)c + 1.0f);
    }
}

// ---------------- smem GEMM machinery ----------------
#define GBM 64

__device__ __forceinline__ void stage_A(const float* __restrict__ A,
                                        float* As, int row_base, int nrows) {
    int tid = threadIdx.x;
    #pragma unroll
    for (int i = tid; i < GBM * 32; i += 256) {
        int r = i >> 5, c = i & 31;
        float4 v = make_float4(0.f, 0.f, 0.f, 0.f);
        if (row_base + r < nrows)
            v = ((const float4*)A)[(size_t)(row_base + r) * 32 + c];
        ((float4*)As)[i] = v;
    }
}
template<int BN>
__device__ __forceinline__ void stage_W(const float* __restrict__ W, float* Ws) {
    int tid = threadIdx.x;
    #pragma unroll
    for (int i = tid; i < 128 * BN / 4; i += 256)
        ((float4*)Ws)[i] = ((const float4*)W)[i];
}

template<int BN, int RPT>
__device__ __forceinline__ void gemm_acc_smem(
    const float* As, const float* Ws,
    int rl0, int col0, unsigned long long (&acc)[RPT][2])
{
    #pragma unroll 4
    for (int k4 = 0; k4 < 128; k4 += 4) {
        F4U2 w0, w1, w2, w3;
        w0.f = *(const float4*)&Ws[(k4 + 0) * BN + col0];
        w1.f = *(const float4*)&Ws[(k4 + 1) * BN + col0];
        w2.f = *(const float4*)&Ws[(k4 + 2) * BN + col0];
        w3.f = *(const float4*)&Ws[(k4 + 3) * BN + col0];
        #pragma unroll
        for (int r = 0; r < RPT; r++) {
            F4U2 a;
            a.f = *(const float4*)&As[(rl0 + r) * 128 + k4];
            unsigned long long ax = dup2(a.s.x), ay = dup2(a.s.y),
                               az = dup2(a.s.z), aw = dup2(a.s.w);
            fma2(acc[r][0], ax, w0.u.lo); fma2(acc[r][1], ax, w0.u.hi);
            fma2(acc[r][0], ay, w1.u.lo); fma2(acc[r][1], ay, w1.u.hi);
            fma2(acc[r][0], az, w2.u.lo); fma2(acc[r][1], az, w2.u.hi);
            fma2(acc[r][0], aw, w3.u.lo); fma2(acc[r][1], aw, w3.u.hi);
        }
    }
}

// ---------------- GCN GEMM + CSR fill (fused launch) ----------------
__device__ __forceinline__ void gemm_body_smem128(
    const float* __restrict__ A, const float* __restrict__ W,
    float* __restrict__ C, int nrows, int bid, float* sm)
{
    constexpr int CT = 32, RPT = 8;
    float* As = sm;
    float* Ws = sm + GBM * 128;
    int row_base = bid * GBM;
    stage_A(A, As, row_base, nrows);
    stage_W<128>(W, Ws);
    __syncthreads();

    const int tid  = threadIdx.x;
    const int tc   = tid % CT;
    const int tr   = tid / CT;
    const int rl0  = tr * RPT;
    const int col0 = tc * 4;

    unsigned long long acc[RPT][2];
    #pragma unroll
    for (int r = 0; r < RPT; r++) { acc[r][0] = 0ull; acc[r][1] = 0ull; }
    gemm_acc_smem<128, RPT>(As, Ws, rl0, col0, acc);

    #pragma unroll
    for (int r = 0; r < RPT; r++) {
        if (row_base + rl0 + r >= nrows) break;
        F4U2 o;
        o.u.lo = acc[r][0]; o.u.hi = acc[r][1];
        *(float4*)&C[(size_t)(row_base + rl0 + r) * 128 + col0] = o.f;
    }
}

__global__ void __launch_bounds__(256) gemm1_fill_k(
    const float* __restrict__ A, const float* __restrict__ W,
    float* __restrict__ C, int nrows, int gb, int E)
{
    extern __shared__ float sm[];
    if ((int)blockIdx.x < gb) {
        gemm_body_smem128(A, W, C, nrows, blockIdx.x, sm);
    } else {
        int e = (blockIdx.x - gb) * 256 + threadIdx.x;
        if (e >= E) return;
        int d = g_dst[e];
        int slot = atomicAdd(&g_cursor[d], 1);
        g_csrc[slot] = g_src[e];
    }
}

// ---------------- mega-fused: SAGE GEMM + value head + 3-layer MLP ----------------
// Per 64-row block: activations stay resident in As smem across 5 GEMM passes.
// Global writes: means + values only.
__global__ void __launch_bounds__(256) mlp_fused_k(
    const float* __restrict__ A1 /*ns*/,  const float* __restrict__ Wl,
    const float* __restrict__ A2 /*h1*/,  const float* __restrict__ Wr,
    const float* __restrict__ bl,
    const float* __restrict__ W1, const float* __restrict__ b1,
    const float* __restrict__ W2, const float* __restrict__ b2,
    const float* __restrict__ W3, const float* __restrict__ b3,
    const float* __restrict__ Wv, const float* __restrict__ bv,
    float* __restrict__ means_out, float* __restrict__ values_out, int nrows)
{
    constexpr int CT = 32, RPT = 8;
    extern __shared__ float sm[];
    float* As = sm;
    float* Ws = sm + GBM * 128;

    const int row_base = blockIdx.x * GBM;
    const int tid  = threadIdx.x;
    const int tc   = tid % CT;
    const int tr   = tid / CT;
    const int rl0  = tr * RPT;
    const int col0 = tc * 4;

    unsigned long long acc[RPT][2];
    #pragma unroll
    for (int r = 0; r < RPT; r++) { acc[r][0] = 0ull; acc[r][1] = 0ull; }

    // --- SAGE pass 1: ns @ Wl ---
    stage_A(A1, As, row_base, nrows);
    stage_W<128>(Wl, Ws);
    __syncthreads();
    gemm_acc_smem<128, RPT>(As, Ws, rl0, col0, acc);
    __syncthreads();
    // --- SAGE pass 2: + h1 @ Wr ---
    stage_A(A2, As, row_base, nrows);
    stage_W<128>(Wr, Ws);
    __syncthreads();
    gemm_acc_smem<128, RPT>(As, Ws, rl0, col0, acc);
    __syncthreads();   // done reading As/Ws

    // --- epilogue: h2 = relu(acc + bl) -> As ; value head ---
    {
        float4 wv = *(const float4*)&Wv[col0];
        float bv0 = bv[0];
        #pragma unroll
        for (int r = 0; r < RPT; r++) {
            F4U2 o;
            o.u.lo = acc[r][0]; o.u.hi = acc[r][1];
            o.s.x = fmaxf(o.s.x + bl[col0 + 0], 0.0f);
            o.s.y = fmaxf(o.s.y + bl[col0 + 1], 0.0f);
            o.s.z = fmaxf(o.s.z + bl[col0 + 2], 0.0f);
            o.s.w = fmaxf(o.s.w + bl[col0 + 3], 0.0f);
            *(float4*)&As[(rl0 + r) * 128 + col0] = o.f;
            float p = fmaf(o.s.x, wv.x, fmaf(o.s.y, wv.y,
                      fmaf(o.s.z, wv.z, o.s.w * wv.w)));
            #pragma unroll
            for (int off = 16; off > 0; off >>= 1)
                p += __shfl_xor_sync(0xFFFFFFFFu, p, off);
            int row = row_base + rl0 + r;
            if (tc == 0 && row < nrows) values_out[row] = p + bv0;
        }
    }
    __syncthreads();

    // --- MLP layers 1 & 2: z = gelu(As @ W + b) -> As ---
    #pragma unroll 1
    for (int layer = 0; layer < 2; layer++) {
        const float* Wp = layer ? W2 : W1;
        const float* bp = layer ? b2 : b1;
        stage_W<128>(Wp, Ws);
        __syncthreads();
        #pragma unroll
        for (int r = 0; r < RPT; r++) { acc[r][0] = 0ull; acc[r][1] = 0ull; }
        gemm_acc_smem<128, RPT>(As, Ws, rl0, col0, acc);
        __syncthreads();
        #pragma unroll
        for (int r = 0; r < RPT; r++) {
            F4U2 o;
            o.u.lo = acc[r][0]; o.u.hi = acc[r][1];
            o.s.x = gelu_f(o.s.x + bp[col0 + 0]);
            o.s.y = gelu_f(o.s.y + bp[col0 + 1]);
            o.s.z = gelu_f(o.s.z + bp[col0 + 2]);
            o.s.w = gelu_f(o.s.w + bp[col0 + 3]);
            *(float4*)&As[(rl0 + r) * 128 + col0] = o.f;
        }
        __syncthreads();
    }

    // --- MLP layer 3 (BN=64): means = As @ W3 + b3 ---
    stage_W<64>(W3, Ws);
    __syncthreads();
    {
        constexpr int CT2 = 16, RPT2 = 4;
        const int tc2   = tid % CT2;
        const int tr2   = tid / CT2;
        const int rl02  = tr2 * RPT2;
        const int col02 = tc2 * 4;
        unsigned long long acc2[RPT2][2];
        #pragma unroll
        for (int r = 0; r < RPT2; r++) { acc2[r][0] = 0ull; acc2[r][1] = 0ull; }
        gemm_acc_smem<64, RPT2>(As, Ws, rl02, col02, acc2);
        #pragma unroll
        for (int r = 0; r < RPT2; r++) {
            int row = row_base + rl02 + r;
            if (row >= nrows) break;
            F4U2 o;
            o.u.lo = acc2[r][0]; o.u.hi = acc2[r][1];
            o.s.x += b3[col02 + 0];
            o.s.y += b3[col02 + 1];
            o.s.z += b3[col02 + 2];
            o.s.w += b3[col02 + 3];
            *(float4*)&means_out[(size_t)row * 64 + col02] = o.f;
        }
    }
}

// ---------------- GCN gather (scalar, 2-edge unroll, MLP=8) ----------------
__global__ void gcn_gather_k(const float* __restrict__ bias, int n) {
    int node = blockIdx.x * (blockDim.x >> 5) + (threadIdx.x >> 5);
    if (node >= n) return;
    int lane = threadIdx.x & 31;
    int beg = g_rowptr[node], end = g_rowptr[node + 1];
    float dd = g_dinv[node];
    const float* xd = g_x + (size_t)node * HID;
    float sl = dd * dd;
    float a0 = xd[lane] * sl;
    float a1 = xd[lane + 32] * sl;
    float a2 = xd[lane + 64] * sl;
    float a3 = xd[lane + 96] * sl;

    int e = beg;
    for (; e + 1 < end; e += 2) {
        int s0 = g_csrc[e], s1 = g_csrc[e + 1];
        float c0 = g_dinv[s0] * dd, c1 = g_dinv[s1] * dd;
        const float* x0 = g_x + (size_t)s0 * HID;
        const float* x1 = g_x + (size_t)s1 * HID;
        float v00 = x0[lane],      v01 = x1[lane];
        float v10 = x0[lane + 32], v11 = x1[lane + 32];
        float v20 = x0[lane + 64], v21 = x1[lane + 64];
        float v30 = x0[lane + 96], v31 = x1[lane + 96];
        a0 = fmaf(v00, c0, a0); a0 = fmaf(v01, c1, a0);
        a1 = fmaf(v10, c0, a1); a1 = fmaf(v11, c1, a1);
        a2 = fmaf(v20, c0, a2); a2 = fmaf(v21, c1, a2);
        a3 = fmaf(v30, c0, a3); a3 = fmaf(v31, c1, a3);
    }
    if (e < end) {
        int s0 = g_csrc[e];
        float c0 = g_dinv[s0] * dd;
        const float* x0 = g_x + (size_t)s0 * HID;
        a0 = fmaf(x0[lane],      c0, a0);
        a1 = fmaf(x0[lane + 32], c0, a1);
        a2 = fmaf(x0[lane + 64], c0, a2);
        a3 = fmaf(x0[lane + 96], c0, a3);
    }
    float* out = g_h1 + (size_t)node * HID;
    out[lane]      = fmaxf(a0 + bias[lane],      0.0f);
    out[lane + 32] = fmaxf(a1 + bias[lane + 32], 0.0f);
    out[lane + 64] = fmaxf(a2 + bias[lane + 64], 0.0f);
    out[lane + 96] = fmaxf(a3 + bias[lane + 96], 0.0f);
}

// ---------------- SAGE gather ----------------
__global__ void sage_gather_k(int n) {
    int node = blockIdx.x * (blockDim.x >> 5) + (threadIdx.x >> 5);
    if (node >= n) return;
    int lane = threadIdx.x & 31;
    int beg = g_rowptr[node], end = g_rowptr[node + 1];
    float a0 = 0.f, a1 = 0.f, a2 = 0.f, a3 = 0.f;
    int e = beg;
    for (; e + 1 < end; e += 2) {
        int s0 = g_csrc[e], s1 = g_csrc[e + 1];
        const float* x0 = g_h1 + (size_t)s0 * HID;
        const float* x1 = g_h1 + (size_t)s1 * HID;
        a0 += x0[lane];      a0 += x1[lane];
        a1 += x0[lane + 32]; a1 += x1[lane + 32];
        a2 += x0[lane + 64]; a2 += x1[lane + 64];
        a3 += x0[lane + 96]; a3 += x1[lane + 96];
    }
    if (e < end) {
        int s0 = g_csrc[e];
        const float* x0 = g_h1 + (size_t)s0 * HID;
        a0 += x0[lane]; a1 += x0[lane + 32]; a2 += x0[lane + 64]; a3 += x0[lane + 96];
    }
    int deg = end - beg;
    float inv = 1.0f / (float)max(deg, 1);
    float* out = g_ns + (size_t)node * HID;
    out[lane]      = a0 * inv;
    out[lane + 32] = a1 * inv;
    out[lane + 64] = a2 * inv;
    out[lane + 96] = a3 * inv;
}

// ---------------- launch ----------------
extern "C" void kernel_launch(void* const* d_in, const int* in_sizes, int n_in,
                              void* d_out, int out_size)
{
    const float* feat     = (const float*)d_in[0];
    const void*  ei       = d_in[1];
    const float* W_gcn    = (const float*)d_in[2];
    const float* b_gcn    = (const float*)d_in[3];
    const float* W_sage_l = (const float*)d_in[4];
    const float* b_sage_l = (const float*)d_in[5];
    const float* W_sage_r = (const float*)d_in[6];
    const float* W1       = (const float*)d_in[7];
    const float* b1       = (const float*)d_in[8];
    const float* W2       = (const float*)d_in[9];
    const float* b2       = (const float*)d_in[10];
    const float* W3       = (const float*)d_in[11];
    const float* b3       = (const float*)d_in[12];
    const float* Wv       = (const float*)d_in[13];
    const float* bv       = (const float*)d_in[14];

    const int N = in_sizes[0] / HID;   // 20000
    const int E = in_sizes[1] / 2;     // 640000

    float* means_out  = (float*)d_out;            // [N, 64]
    float* values_out = (float*)d_out + (size_t)N * 64;

    float *p_x, *p_h1, *p_ns;
    cudaGetSymbolAddress((void**)&p_x,  g_x);
    cudaGetSymbolAddress((void**)&p_h1, g_h1);
    cudaGetSymbolAddress((void**)&p_ns, g_ns);

    const int TB = 256;
    const int e_blocks    = (E + TB - 1) / TB;        // 2500
    const int nw_blocks   = (N * 32 + TB - 1) / TB;   // warp per node
    const int scan_blocks = (N + 1023) / 1024;        // 20
    const int gemm_blocks = (N + GBM - 1) / GBM;      // 313

    const int SM128 = (GBM * 128 + 128 * 128) * 4;    // 96 KB
    static int attrs_set = 0;
    if (!attrs_set) {
        cudaFuncSetAttribute(gemm1_fill_k,
            cudaFuncAttributeMaxDynamicSharedMemorySize, SM128);
        cudaFuncSetAttribute(mlp_fused_k,
            cudaFuncAttributeMaxDynamicSharedMemorySize, SM128);
        attrs_set = 1;
    }

    init_k<<<80, TB>>>((const int*)ei, N);
    convert_count_k<<<e_blocks, TB>>>(ei, E);
    scan_fused_k<<<scan_blocks, 1024>>>(N);
    gemm1_fill_k<<<gemm_blocks + e_blocks, TB, SM128>>>(feat, W_gcn, p_x, N,
                                                        gemm_blocks, E);
    gcn_gather_k<<<nw_blocks, TB>>>(b_gcn, N);
    sage_gather_k<<<nw_blocks, TB>>>(N);
    mlp_fused_k<<<gemm_blocks, TB, SM128>>>(p_ns, W_sage_l, p_h1, W_sage_r,
                                            b_sage_l, W1, b1, W2, b2, W3, b3,
                                            Wv, bv, means_out, values_out, N);
}

// round 12
// speedup vs baseline: 1.3053x; 1.0023x over previous
#include <cuda_runtime.h>
#include <math.h>

#define NN 20000
#define EE 640000
#define HID 128

// ---------------- scratch (device globals; no allocation) ----------------
__device__ int   g_is64;
__device__ int   g_flag;
__device__ int   g_src[EE];
__device__ int   g_dst[EE];
__device__ int   g_csrc[EE];
__device__ int   g_icnt[NN];
__device__ int   g_rowptr[NN + 1];
__device__ int   g_cursor[NN];
__device__ int   g_part[64];
__device__ float g_dinv[NN];
__device__ float g_x  [NN * HID];
__device__ float g_h1 [NN * HID];
__device__ float g_ns [NN * HID];

// ---------------- small helpers ----------------
__device__ __forceinline__ float gelu_f(float x) {
    return 0.5f * x * (1.0f + erff(x * 0.70710678118654752440f));
}
__device__ __forceinline__ void fma2(unsigned long long& acc,
                                     unsigned long long a, unsigned long long b) {
    asm("fma.rn.f32x2 %0, %1, %2, %0;" : "+l"(acc) : "l"(a), "l"(b));
}
__device__ __forceinline__ unsigned long long dup2(float a) {
    unsigned long long r;
    asm("mov.b64 %0, {%1, %1};" : "=l"(r) : "f"(a));
    return r;
}
union F4U2 {
    float4 f;
    struct { unsigned long long lo, hi; } u;
    struct { float x, y, z, w; } s;
};

// ---------------- init ----------------
__global__ void init_k(const int* __restrict__ ei_words, int n) {
    int idx = blockIdx.x * blockDim.x + threadIdx.x;
    int stride = gridDim.x * blockDim.x;
    for (int i = idx; i < n; i += stride) g_icnt[i] = 0;
    if (idx == 0) g_flag = 0;
    if (blockIdx.x == 0 && threadIdx.x < 64) {
        int hi = ei_words[2 * threadIdx.x + 1];
        __shared__ unsigned s[2];
        unsigned b = __ballot_sync(0xFFFFFFFFu, hi != 0);
        if ((threadIdx.x & 31) == 0) s[threadIdx.x >> 5] = b;
        __syncthreads();
        if (threadIdx.x == 0) g_is64 = ((s[0] | s[1]) == 0u) ? 1 : 0;
    }
}

__global__ void convert_count_k(const void* __restrict__ ei, int E) {
    int e = blockIdx.x * blockDim.x + threadIdx.x;
    if (e >= E) return;
    int s, d;
    if (g_is64) {
        const long long* p = (const long long*)ei;
        s = (int)p[e]; d = (int)p[E + e];
    } else {
        const int* p = (const int*)ei;
        s = p[e]; d = p[E + e];
    }
    g_src[e] = s;
    g_dst[e] = d;
    atomicAdd(&g_icnt[d], 1);
}

// ---------------- single-launch scan ----------------
__global__ void __launch_bounds__(1024) scan_fused_k(int n) {
    __shared__ int wsum[32];
    __shared__ int s_off;
    int tid = threadIdx.x, lane = tid & 31, wid = tid >> 5;
    int i = blockIdx.x * 1024 + tid;
    int c = (i < n) ? g_icnt[i] : 0;
    int incl = c;
    #pragma unroll
    for (int off = 1; off < 32; off <<= 1) {
        int u = __shfl_up_sync(0xFFFFFFFFu, incl, off);
        if (lane >= off) incl += u;
    }
    if (lane == 31) wsum[wid] = incl;
    __syncthreads();
    if (wid == 0) {
        int t = wsum[lane];
        #pragma unroll
        for (int off = 1; off < 32; off <<= 1) {
            int u = __shfl_up_sync(0xFFFFFFFFu, t, off);
            if (lane >= off) t += u;
        }
        wsum[lane] = t;
    }
    __syncthreads();
    int warp_off = (wid == 0) ? 0 : wsum[wid - 1];
    int local_excl = warp_off + incl - c;
    int block_total = wsum[31];

    if (tid == 0) {
        g_part[blockIdx.x] = block_total;
        __threadfence();
        atomicAdd(&g_flag, 1);
        while (atomicAdd(&g_flag, 0) < (int)gridDim.x) { }
        __threadfence();
        int o = 0;
        for (int b = 0; b < (int)blockIdx.x; b++) o += g_part[b];
        s_off = o;
        if (blockIdx.x == gridDim.x - 1) g_rowptr[n] = o + block_total;
    }
    __syncthreads();
    int run = s_off + local_excl;
    if (i < n) {
        g_rowptr[i] = run;
        g_cursor[i] = run;
        g_dinv[i]   = rsqrtf((float)c + 1.0f);
    }
}

// CSR fill (on side stream, overlapped with GEMM1)
__global__ void fill_k(int E) {
    int e = blockIdx.x * blockDim.x + threadIdx.x;
    if (e >= E) return;
    int d = g_dst[e];
    int slot = atomicAdd(&g_cursor[d], 1);
    g_csrc[slot] = g_src[e];
}

// ---------------- smem GEMM machinery ----------------
#define GBM 64

__device__ __forceinline__ void stage_A(const float* __restrict__ A,
                                        float* As, int row_base, int nrows) {
    int tid = threadIdx.x;
    #pragma unroll
    for (int i = tid; i < GBM * 32; i += 256) {
        int r = i >> 5, c = i & 31;
        float4 v = make_float4(0.f, 0.f, 0.f, 0.f);
        if (row_base + r < nrows)
            v = ((const float4*)A)[(size_t)(row_base + r) * 32 + c];
        ((float4*)As)[i] = v;
    }
}
template<int BN>
__device__ __forceinline__ void stage_W(const float* __restrict__ W, float* Ws) {
    int tid = threadIdx.x;
    #pragma unroll
    for (int i = tid; i < 128 * BN / 4; i += 256)
        ((float4*)Ws)[i] = ((const float4*)W)[i];
}

template<int BN, int RPT>
__device__ __forceinline__ void gemm_acc_smem(
    const float* As, const float* Ws,
    int rl0, int col0, unsigned long long (&acc)[RPT][2])
{
    #pragma unroll 4
    for (int k4 = 0; k4 < 128; k4 += 4) {
        F4U2 w0, w1, w2, w3;
        w0.f = *(const float4*)&Ws[(k4 + 0) * BN + col0];
        w1.f = *(const float4*)&Ws[(k4 + 1) * BN + col0];
        w2.f = *(const float4*)&Ws[(k4 + 2) * BN + col0];
        w3.f = *(const float4*)&Ws[(k4 + 3) * BN + col0];
        #pragma unroll
        for (int r = 0; r < RPT; r++) {
            F4U2 a;
            a.f = *(const float4*)&As[(rl0 + r) * 128 + k4];
            unsigned long long ax = dup2(a.s.x), ay = dup2(a.s.y),
                               az = dup2(a.s.z), aw = dup2(a.s.w);
            fma2(acc[r][0], ax, w0.u.lo); fma2(acc[r][1], ax, w0.u.hi);
            fma2(acc[r][0], ay, w1.u.lo); fma2(acc[r][1], ay, w1.u.hi);
            fma2(acc[r][0], az, w2.u.lo); fma2(acc[r][1], az, w2.u.hi);
            fma2(acc[r][0], aw, w3.u.lo); fma2(acc[r][1], aw, w3.u.hi);
        }
    }
}

// ---------------- GEMM1: x = feat @ W_gcn ----------------
__global__ void __launch_bounds__(256) gemm1_k(
    const float* __restrict__ A, const float* __restrict__ W,
    float* __restrict__ C, int nrows)
{
    constexpr int CT = 32, RPT = 8;
    extern __shared__ float sm[];
    float* As = sm;
    float* Ws = sm + GBM * 128;
    int row_base = blockIdx.x * GBM;
    stage_A(A, As, row_base, nrows);
    stage_W<128>(W, Ws);
    __syncthreads();

    const int tid  = threadIdx.x;
    const int tc   = tid % CT;
    const int tr   = tid / CT;
    const int rl0  = tr * RPT;
    const int col0 = tc * 4;

    unsigned long long acc[RPT][2];
    #pragma unroll
    for (int r = 0; r < RPT; r++) { acc[r][0] = 0ull; acc[r][1] = 0ull; }
    gemm_acc_smem<128, RPT>(As, Ws, rl0, col0, acc);

    #pragma unroll
    for (int r = 0; r < RPT; r++) {
        if (row_base + rl0 + r >= nrows) break;
        F4U2 o;
        o.u.lo = acc[r][0]; o.u.hi = acc[r][1];
        *(float4*)&C[(size_t)(row_base + rl0 + r) * 128 + col0] = o.f;
    }
}

// ---------------- mega-fused: SAGE GEMM + value head + 3-layer MLP ----------------
__global__ void __launch_bounds__(256) mlp_fused_k(
    const float* __restrict__ A1 /*ns*/,  const float* __restrict__ Wl,
    const float* __restrict__ A2 /*h1*/,  const float* __restrict__ Wr,
    const float* __restrict__ bl,
    const float* __restrict__ W1, const float* __restrict__ b1,
    const float* __restrict__ W2, const float* __restrict__ b2,
    const float* __restrict__ W3, const float* __restrict__ b3,
    const float* __restrict__ Wv, const float* __restrict__ bv,
    float* __restrict__ means_out, float* __restrict__ values_out, int nrows)
{
    constexpr int CT = 32, RPT = 8;
    extern __shared__ float sm[];
    float* As = sm;
    float* Ws = sm + GBM * 128;

    const int row_base = blockIdx.x * GBM;
    const int tid  = threadIdx.x;
    const int tc   = tid % CT;
    const int tr   = tid / CT;
    const int rl0  = tr * RPT;
    const int col0 = tc * 4;

    unsigned long long acc[RPT][2];
    #pragma unroll
    for (int r = 0; r < RPT; r++) { acc[r][0] = 0ull; acc[r][1] = 0ull; }

    // --- SAGE pass 1: ns @ Wl ---
    stage_A(A1, As, row_base, nrows);
    stage_W<128>(Wl, Ws);
    __syncthreads();
    gemm_acc_smem<128, RPT>(As, Ws, rl0, col0, acc);
    __syncthreads();
    // --- SAGE pass 2: + h1 @ Wr ---
    stage_A(A2, As, row_base, nrows);
    stage_W<128>(Wr, Ws);
    __syncthreads();
    gemm_acc_smem<128, RPT>(As, Ws, rl0, col0, acc);
    __syncthreads();

    // --- epilogue: h2 = relu(acc + bl) -> As ; value head ---
    {
        float4 wv = *(const float4*)&Wv[col0];
        float bv0 = bv[0];
        #pragma unroll
        for (int r = 0; r < RPT; r++) {
            F4U2 o;
            o.u.lo = acc[r][0]; o.u.hi = acc[r][1];
            o.s.x = fmaxf(o.s.x + bl[col0 + 0], 0.0f);
            o.s.y = fmaxf(o.s.y + bl[col0 + 1], 0.0f);
            o.s.z = fmaxf(o.s.z + bl[col0 + 2], 0.0f);
            o.s.w = fmaxf(o.s.w + bl[col0 + 3], 0.0f);
            *(float4*)&As[(rl0 + r) * 128 + col0] = o.f;
            float p = fmaf(o.s.x, wv.x, fmaf(o.s.y, wv.y,
                      fmaf(o.s.z, wv.z, o.s.w * wv.w)));
            #pragma unroll
            for (int off = 16; off > 0; off >>= 1)
                p += __shfl_xor_sync(0xFFFFFFFFu, p, off);
            int row = row_base + rl0 + r;
            if (tc == 0 && row < nrows) values_out[row] = p + bv0;
        }
    }
    __syncthreads();

    // --- MLP layers 1 & 2: z = gelu(As @ W + b) -> As ---
    #pragma unroll 1
    for (int layer = 0; layer < 2; layer++) {
        const float* Wp = layer ? W2 : W1;
        const float* bp = layer ? b2 : b1;
        stage_W<128>(Wp, Ws);
        __syncthreads();
        #pragma unroll
        for (int r = 0; r < RPT; r++) { acc[r][0] = 0ull; acc[r][1] = 0ull; }
        gemm_acc_smem<128, RPT>(As, Ws, rl0, col0, acc);
        __syncthreads();
        #pragma unroll
        for (int r = 0; r < RPT; r++) {
            F4U2 o;
            o.u.lo = acc[r][0]; o.u.hi = acc[r][1];
            o.s.x = gelu_f(o.s.x + bp[col0 + 0]);
            o.s.y = gelu_f(o.s.y + bp[col0 + 1]);
            o.s.z = gelu_f(o.s.z + bp[col0 + 2]);
            o.s.w = gelu_f(o.s.w + bp[col0 + 3]);
            *(float4*)&As[(rl0 + r) * 128 + col0] = o.f;
        }
        __syncthreads();
    }

    // --- MLP layer 3 (BN=64): means = As @ W3 + b3 ---
    stage_W<64>(W3, Ws);
    __syncthreads();
    {
        constexpr int CT2 = 16, RPT2 = 4;
        const int tc2   = tid % CT2;
        const int tr2   = tid / CT2;
        const int rl02  = tr2 * RPT2;
        const int col02 = tc2 * 4;
        unsigned long long acc2[RPT2][2];
        #pragma unroll
        for (int r = 0; r < RPT2; r++) { acc2[r][0] = 0ull; acc2[r][1] = 0ull; }
        gemm_acc_smem<64, RPT2>(As, Ws, rl02, col02, acc2);
        #pragma unroll
        for (int r = 0; r < RPT2; r++) {
            int row = row_base + rl02 + r;
            if (row >= nrows) break;
            F4U2 o;
            o.u.lo = acc2[r][0]; o.u.hi = acc2[r][1];
            o.s.x += b3[col02 + 0];
            o.s.y += b3[col02 + 1];
            o.s.z += b3[col02 + 2];
            o.s.w += b3[col02 + 3];
            *(float4*)&means_out[(size_t)row * 64 + col02] = o.f;
        }
    }
}

// ---------------- GCN gather (scalar, 2-edge unroll, MLP=8) ----------------
__global__ void gcn_gather_k(const float* __restrict__ bias, int n) {
    int node = blockIdx.x * (blockDim.x >> 5) + (threadIdx.x >> 5);
    if (node >= n) return;
    int lane = threadIdx.x & 31;
    int beg = g_rowptr[node], end = g_rowptr[node + 1];
    float dd = g_dinv[node];
    const float* xd = g_x + (size_t)node * HID;
    float sl = dd * dd;
    float a0 = xd[lane] * sl;
    float a1 = xd[lane + 32] * sl;
    float a2 = xd[lane + 64] * sl;
    float a3 = xd[lane + 96] * sl;

    int e = beg;
    for (; e + 1 < end; e += 2) {
        int s0 = g_csrc[e], s1 = g_csrc[e + 1];
        float c0 = g_dinv[s0] * dd, c1 = g_dinv[s1] * dd;
        const float* x0 = g_x + (size_t)s0 * HID;
        const float* x1 = g_x + (size_t)s1 * HID;
        float v00 = x0[lane],      v01 = x1[lane];
        float v10 = x0[lane + 32], v11 = x1[lane + 32];
        float v20 = x0[lane + 64], v21 = x1[lane + 64];
        float v30 = x0[lane + 96], v31 = x1[lane + 96];
        a0 = fmaf(v00, c0, a0); a0 = fmaf(v01, c1, a0);
        a1 = fmaf(v10, c0, a1); a1 = fmaf(v11, c1, a1);
        a2 = fmaf(v20, c0, a2); a2 = fmaf(v21, c1, a2);
        a3 = fmaf(v30, c0, a3); a3 = fmaf(v31, c1, a3);
    }
    if (e < end) {
        int s0 = g_csrc[e];
        float c0 = g_dinv[s0] * dd;
        const float* x0 = g_x + (size_t)s0 * HID;
        a0 = fmaf(x0[lane],      c0, a0);
        a1 = fmaf(x0[lane + 32], c0, a1);
        a2 = fmaf(x0[lane + 64], c0, a2);
        a3 = fmaf(x0[lane + 96], c0, a3);
    }
    float* out = g_h1 + (size_t)node * HID;
    out[lane]      = fmaxf(a0 + bias[lane],      0.0f);
    out[lane + 32] = fmaxf(a1 + bias[lane + 32], 0.0f);
    out[lane + 64] = fmaxf(a2 + bias[lane + 64], 0.0f);
    out[lane + 96] = fmaxf(a3 + bias[lane + 96], 0.0f);
}

// ---------------- SAGE gather ----------------
__global__ void sage_gather_k(int n) {
    int node = blockIdx.x * (blockDim.x >> 5) + (threadIdx.x >> 5);
    if (node >= n) return;
    int lane = threadIdx.x & 31;
    int beg = g_rowptr[node], end = g_rowptr[node + 1];
    float a0 = 0.f, a1 = 0.f, a2 = 0.f, a3 = 0.f;
    int e = beg;
    for (; e + 1 < end; e += 2) {
        int s0 = g_csrc[e], s1 = g_csrc[e + 1];
        const float* x0 = g_h1 + (size_t)s0 * HID;
        const float* x1 = g_h1 + (size_t)s1 * HID;
        a0 += x0[lane];      a0 += x1[lane];
        a1 += x0[lane + 32]; a1 += x1[lane + 32];
        a2 += x0[lane + 64]; a2 += x1[lane + 64];
        a3 += x0[lane + 96]; a3 += x1[lane + 96];
    }
    if (e < end) {
        int s0 = g_csrc[e];
        const float* x0 = g_h1 + (size_t)s0 * HID;
        a0 += x0[lane]; a1 += x0[lane + 32]; a2 += x0[lane + 64]; a3 += x0[lane + 96];
    }
    int deg = end - beg;
    float inv = 1.0f / (float)max(deg, 1);
    float* out = g_ns + (size_t)node * HID;
    out[lane]      = a0 * inv;
    out[lane + 32] = a1 * inv;
    out[lane + 64] = a2 * inv;
    out[lane + 96] = a3 * inv;
}

// ---------------- launch ----------------
extern "C" void kernel_launch(void* const* d_in, const int* in_sizes, int n_in,
                              void* d_out, int out_size)
{
    const float* feat     = (const float*)d_in[0];
    const void*  ei       = d_in[1];
    const float* W_gcn    = (const float*)d_in[2];
    const float* b_gcn    = (const float*)d_in[3];
    const float* W_sage_l = (const float*)d_in[4];
    const float* b_sage_l = (const float*)d_in[5];
    const float* W_sage_r = (const float*)d_in[6];
    const float* W1       = (const float*)d_in[7];
    const float* b1       = (const float*)d_in[8];
    const float* W2       = (const float*)d_in[9];
    const float* b2       = (const float*)d_in[10];
    const float* W3       = (const float*)d_in[11];
    const float* b3       = (const float*)d_in[12];
    const float* Wv       = (const float*)d_in[13];
    const float* bv       = (const float*)d_in[14];

    const int N = in_sizes[0] / HID;   // 20000
    const int E = in_sizes[1] / 2;     // 640000

    float* means_out  = (float*)d_out;            // [N, 64]
    float* values_out = (float*)d_out + (size_t)N * 64;

    float *p_x, *p_h1, *p_ns;
    cudaGetSymbolAddress((void**)&p_x,  g_x);
    cudaGetSymbolAddress((void**)&p_h1, g_h1);
    cudaGetSymbolAddress((void**)&p_ns, g_ns);

    const int TB = 256;
    const int e_blocks    = (E + TB - 1) / TB;        // 2500
    const int nw_blocks   = (N * 32 + TB - 1) / TB;   // warp per node
    const int scan_blocks = (N + 1023) / 1024;        // 20
    const int gemm_blocks = (N + GBM - 1) / GBM;      // 313

    const int SM128 = (GBM * 128 + 128 * 128) * 4;    // 96 KB

    // one-time setup: smem attrs + side stream + fork/join events
    static int init_done = 0;
    static cudaStream_t s2;
    static cudaEvent_t ev_fork, ev_join;
    if (!init_done) {
        cudaFuncSetAttribute(gemm1_k,
            cudaFuncAttributeMaxDynamicSharedMemorySize, SM128);
        cudaFuncSetAttribute(mlp_fused_k,
            cudaFuncAttributeMaxDynamicSharedMemorySize, SM128);
        cudaStreamCreateWithFlags(&s2, cudaStreamNonBlocking);
        cudaEventCreateWithFlags(&ev_fork, cudaEventDisableTiming);
        cudaEventCreateWithFlags(&ev_join, cudaEventDisableTiming);
        init_done = 1;
    }

    // fork: CSR build chain on s2, GEMM1 on main stream — independent
    cudaEventRecord(ev_fork, 0);
    cudaStreamWaitEvent(s2, ev_fork, 0);

    init_k<<<80, TB, 0, s2>>>((const int*)ei, N);
    convert_count_k<<<e_blocks, TB, 0, s2>>>(ei, E);
    scan_fused_k<<<scan_blocks, 1024, 0, s2>>>(N);
    fill_k<<<e_blocks, TB, 0, s2>>>(E);
    cudaEventRecord(ev_join, s2);

    gemm1_k<<<gemm_blocks, TB, SM128>>>(feat, W_gcn, p_x, N);

    // join: gathers need both CSR and g_x
    cudaStreamWaitEvent(0, ev_join, 0);
    gcn_gather_k<<<nw_blocks, TB>>>(b_gcn, N);
    sage_gather_k<<<nw_blocks, TB>>>(N);
    mlp_fused_k<<<gemm_blocks, TB, SM128>>>(p_ns, W_sage_l, p_h1, W_sage_r,
                                            b_sage_l, W1, b1, W2, b2, W3, b3,
                                            Wv, bv, means_out, values_out, N);
}

// round 13
// speedup vs baseline: 1.3975x; 1.0706x over previous
#include <cuda_runtime.h>
#include <cuda_fp16.h>
#include <math.h>

#define NN 20000
#define EE 640000
#define HID 128

// ---------------- scratch (device globals; no allocation) ----------------
__device__ int    g_is64;
__device__ int    g_flag;
__device__ int    g_src[EE];
__device__ int    g_dst[EE];
__device__ int    g_csrc[EE];
__device__ int    g_icnt[NN];
__device__ int    g_rowptr[NN + 1];
__device__ int    g_cursor[NN];
__device__ int    g_part[64];
__device__ float  g_dinv[NN];
__device__ __half g_x16 [NN * HID];   // feat@W_gcn, fp16 (gather payload)
__device__ float  g_h1  [NN * HID];   // GCN out, fp32 (SAGE-root GEMM input)
__device__ __half g_h116[NN * HID];   // GCN out, fp16 (SAGE gather payload)
__device__ float  g_ns  [NN * HID];   // SAGE neighbor mean, fp32

// ---------------- small helpers ----------------
__device__ __forceinline__ float gelu_f(float x) {
    return 0.5f * x * (1.0f + erff(x * 0.70710678118654752440f));
}
__device__ __forceinline__ void fma2(unsigned long long& acc,
                                     unsigned long long a, unsigned long long b) {
    asm("fma.rn.f32x2 %0, %1, %2, %0;" : "+l"(acc) : "l"(a), "l"(b));
}
__device__ __forceinline__ unsigned long long dup2(float a) {
    unsigned long long r;
    asm("mov.b64 %0, {%1, %1};" : "=l"(r) : "f"(a));
    return r;
}
union F4U2 {
    float4 f;
    struct { unsigned long long lo, hi; } u;
    struct { float x, y, z, w; } s;
};

// 4 halfs (uint2) -> float4
__device__ __forceinline__ float4 h4_to_f4(uint2 u) {
    __half2 a = *(__half2*)&u.x, b = *(__half2*)&u.y;
    float2 fa = __half22float2(a), fb = __half22float2(b);
    return make_float4(fa.x, fa.y, fb.x, fb.y);
}
// float4 -> 4 halfs (uint2)
__device__ __forceinline__ uint2 f4_to_h4(float4 f) {
    __half2 a = __floats2half2_rn(f.x, f.y), b = __floats2half2_rn(f.z, f.w);
    uint2 u;
    u.x = *(unsigned*)&a; u.y = *(unsigned*)&b;
    return u;
}

// ---------------- init ----------------
__global__ void init_k(const int* __restrict__ ei_words, int n) {
    int idx = blockIdx.x * blockDim.x + threadIdx.x;
    int stride = gridDim.x * blockDim.x;
    for (int i = idx; i < n; i += stride) g_icnt[i] = 0;
    if (idx == 0) g_flag = 0;
    if (blockIdx.x == 0 && threadIdx.x < 64) {
        int hi = ei_words[2 * threadIdx.x + 1];
        __shared__ unsigned s[2];
        unsigned b = __ballot_sync(0xFFFFFFFFu, hi != 0);
        if ((threadIdx.x & 31) == 0) s[threadIdx.x >> 5] = b;
        __syncthreads();
        if (threadIdx.x == 0) g_is64 = ((s[0] | s[1]) == 0u) ? 1 : 0;
    }
}

__global__ void convert_count_k(const void* __restrict__ ei, int E) {
    int e = blockIdx.x * blockDim.x + threadIdx.x;
    if (e >= E) return;
    int s, d;
    if (g_is64) {
        const long long* p = (const long long*)ei;
        s = (int)p[e]; d = (int)p[E + e];
    } else {
        const int* p = (const int*)ei;
        s = p[e]; d = p[E + e];
    }
    g_src[e] = s;
    g_dst[e] = d;
    atomicAdd(&g_icnt[d], 1);
}

// ---------------- single-launch scan ----------------
__global__ void __launch_bounds__(1024) scan_fused_k(int n) {
    __shared__ int wsum[32];
    __shared__ int s_off;
    int tid = threadIdx.x, lane = tid & 31, wid = tid >> 5;
    int i = blockIdx.x * 1024 + tid;
    int c = (i < n) ? g_icnt[i] : 0;
    int incl = c;
    #pragma unroll
    for (int off = 1; off < 32; off <<= 1) {
        int u = __shfl_up_sync(0xFFFFFFFFu, incl, off);
        if (lane >= off) incl += u;
    }
    if (lane == 31) wsum[wid] = incl;
    __syncthreads();
    if (wid == 0) {
        int t = wsum[lane];
        #pragma unroll
        for (int off = 1; off < 32; off <<= 1) {
            int u = __shfl_up_sync(0xFFFFFFFFu, t, off);
            if (lane >= off) t += u;
        }
        wsum[lane] = t;
    }
    __syncthreads();
    int warp_off = (wid == 0) ? 0 : wsum[wid - 1];
    int local_excl = warp_off + incl - c;
    int block_total = wsum[31];

    if (tid == 0) {
        g_part[blockIdx.x] = block_total;
        __threadfence();
        atomicAdd(&g_flag, 1);
        while (atomicAdd(&g_flag, 0) < (int)gridDim.x) { }
        __threadfence();
        int o = 0;
        for (int b = 0; b < (int)blockIdx.x; b++) o += g_part[b];
        s_off = o;
        if (blockIdx.x == gridDim.x - 1) g_rowptr[n] = o + block_total;
    }
    __syncthreads();
    int run = s_off + local_excl;
    if (i < n) {
        g_rowptr[i] = run;
        g_cursor[i] = run;
        g_dinv[i]   = rsqrtf((float)c + 1.0f);
    }
}

__global__ void fill_k(int E) {
    int e = blockIdx.x * blockDim.x + threadIdx.x;
    if (e >= E) return;
    int d = g_dst[e];
    int slot = atomicAdd(&g_cursor[d], 1);
    g_csrc[slot] = g_src[e];
}

// ---------------- smem GEMM machinery ----------------
#define GBM 64

__device__ __forceinline__ void stage_A(const float* __restrict__ A,
                                        float* As, int row_base, int nrows) {
    int tid = threadIdx.x;
    #pragma unroll
    for (int i = tid; i < GBM * 32; i += 256) {
        int r = i >> 5, c = i & 31;
        float4 v = make_float4(0.f, 0.f, 0.f, 0.f);
        if (row_base + r < nrows)
            v = ((const float4*)A)[(size_t)(row_base + r) * 32 + c];
        ((float4*)As)[i] = v;
    }
}
template<int BN>
__device__ __forceinline__ void stage_W(const float* __restrict__ W, float* Ws) {
    int tid = threadIdx.x;
    #pragma unroll
    for (int i = tid; i < 128 * BN / 4; i += 256)
        ((float4*)Ws)[i] = ((const float4*)W)[i];
}

template<int BN, int RPT>
__device__ __forceinline__ void gemm_acc_smem(
    const float* As, const float* Ws,
    int rl0, int col0, unsigned long long (&acc)[RPT][2])
{
    #pragma unroll 4
    for (int k4 = 0; k4 < 128; k4 += 4) {
        F4U2 w0, w1, w2, w3;
        w0.f = *(const float4*)&Ws[(k4 + 0) * BN + col0];
        w1.f = *(const float4*)&Ws[(k4 + 1) * BN + col0];
        w2.f = *(const float4*)&Ws[(k4 + 2) * BN + col0];
        w3.f = *(const float4*)&Ws[(k4 + 3) * BN + col0];
        #pragma unroll
        for (int r = 0; r < RPT; r++) {
            F4U2 a;
            a.f = *(const float4*)&As[(rl0 + r) * 128 + k4];
            unsigned long long ax = dup2(a.s.x), ay = dup2(a.s.y),
                               az = dup2(a.s.z), aw = dup2(a.s.w);
            fma2(acc[r][0], ax, w0.u.lo); fma2(acc[r][1], ax, w0.u.hi);
            fma2(acc[r][0], ay, w1.u.lo); fma2(acc[r][1], ay, w1.u.hi);
            fma2(acc[r][0], az, w2.u.lo); fma2(acc[r][1], az, w2.u.hi);
            fma2(acc[r][0], aw, w3.u.lo); fma2(acc[r][1], aw, w3.u.hi);
        }
    }
}

// ---------------- GEMM1: x16 = fp16(feat @ W_gcn) ----------------
__global__ void __launch_bounds__(256) gemm1_k(
    const float* __restrict__ A, const float* __restrict__ W, int nrows)
{
    constexpr int CT = 32, RPT = 8;
    extern __shared__ float sm[];
    float* As = sm;
    float* Ws = sm + GBM * 128;
    int row_base = blockIdx.x * GBM;
    stage_A(A, As, row_base, nrows);
    stage_W<128>(W, Ws);
    __syncthreads();

    const int tid  = threadIdx.x;
    const int tc   = tid % CT;
    const int tr   = tid / CT;
    const int rl0  = tr * RPT;
    const int col0 = tc * 4;

    unsigned long long acc[RPT][2];
    #pragma unroll
    for (int r = 0; r < RPT; r++) { acc[r][0] = 0ull; acc[r][1] = 0ull; }
    gemm_acc_smem<128, RPT>(As, Ws, rl0, col0, acc);

    #pragma unroll
    for (int r = 0; r < RPT; r++) {
        int row = row_base + rl0 + r;
        if (row >= nrows) break;
        F4U2 o;
        o.u.lo = acc[r][0]; o.u.hi = acc[r][1];
        *(uint2*)&g_x16[(size_t)row * 128 + col0] = f4_to_h4(o.f);
    }
}

// ---------------- mega-fused: SAGE GEMM + value head + 3-layer MLP ----------------
__global__ void __launch_bounds__(256) mlp_fused_k(
    const float* __restrict__ A1 /*ns*/,  const float* __restrict__ Wl,
    const float* __restrict__ A2 /*h1*/,  const float* __restrict__ Wr,
    const float* __restrict__ bl,
    const float* __restrict__ W1, const float* __restrict__ b1,
    const float* __restrict__ W2, const float* __restrict__ b2,
    const float* __restrict__ W3, const float* __restrict__ b3,
    const float* __restrict__ Wv, const float* __restrict__ bv,
    float* __restrict__ means_out, float* __restrict__ values_out, int nrows)
{
    constexpr int CT = 32, RPT = 8;
    extern __shared__ float sm[];
    float* As = sm;
    float* Ws = sm + GBM * 128;

    const int row_base = blockIdx.x * GBM;
    const int tid  = threadIdx.x;
    const int tc   = tid % CT;
    const int tr   = tid / CT;
    const int rl0  = tr * RPT;
    const int col0 = tc * 4;

    unsigned long long acc[RPT][2];
    #pragma unroll
    for (int r = 0; r < RPT; r++) { acc[r][0] = 0ull; acc[r][1] = 0ull; }

    // --- SAGE pass 1: ns @ Wl ---
    stage_A(A1, As, row_base, nrows);
    stage_W<128>(Wl, Ws);
    __syncthreads();
    gemm_acc_smem<128, RPT>(As, Ws, rl0, col0, acc);
    __syncthreads();
    // --- SAGE pass 2: + h1 @ Wr ---
    stage_A(A2, As, row_base, nrows);
    stage_W<128>(Wr, Ws);
    __syncthreads();
    gemm_acc_smem<128, RPT>(As, Ws, rl0, col0, acc);
    __syncthreads();

    // --- epilogue: h2 = relu(acc + bl) -> As ; value head ---
    {
        float4 wv = *(const float4*)&Wv[col0];
        float bv0 = bv[0];
        #pragma unroll
        for (int r = 0; r < RPT; r++) {
            F4U2 o;
            o.u.lo = acc[r][0]; o.u.hi = acc[r][1];
            o.s.x = fmaxf(o.s.x + bl[col0 + 0], 0.0f);
            o.s.y = fmaxf(o.s.y + bl[col0 + 1], 0.0f);
            o.s.z = fmaxf(o.s.z + bl[col0 + 2], 0.0f);
            o.s.w = fmaxf(o.s.w + bl[col0 + 3], 0.0f);
            *(float4*)&As[(rl0 + r) * 128 + col0] = o.f;
            float p = fmaf(o.s.x, wv.x, fmaf(o.s.y, wv.y,
                      fmaf(o.s.z, wv.z, o.s.w * wv.w)));
            #pragma unroll
            for (int off = 16; off > 0; off >>= 1)
                p += __shfl_xor_sync(0xFFFFFFFFu, p, off);
            int row = row_base + rl0 + r;
            if (tc == 0 && row < nrows) values_out[row] = p + bv0;
        }
    }
    __syncthreads();

    // --- MLP layers 1 & 2: z = gelu(As @ W + b) -> As ---
    #pragma unroll 1
    for (int layer = 0; layer < 2; layer++) {
        const float* Wp = layer ? W2 : W1;
        const float* bp = layer ? b2 : b1;
        stage_W<128>(Wp, Ws);
        __syncthreads();
        #pragma unroll
        for (int r = 0; r < RPT; r++) { acc[r][0] = 0ull; acc[r][1] = 0ull; }
        gemm_acc_smem<128, RPT>(As, Ws, rl0, col0, acc);
        __syncthreads();
        #pragma unroll
        for (int r = 0; r < RPT; r++) {
            F4U2 o;
            o.u.lo = acc[r][0]; o.u.hi = acc[r][1];
            o.s.x = gelu_f(o.s.x + bp[col0 + 0]);
            o.s.y = gelu_f(o.s.y + bp[col0 + 1]);
            o.s.z = gelu_f(o.s.z + bp[col0 + 2]);
            o.s.w = gelu_f(o.s.w + bp[col0 + 3]);
            *(float4*)&As[(rl0 + r) * 128 + col0] = o.f;
        }
        __syncthreads();
    }

    // --- MLP layer 3 (BN=64): means = As @ W3 + b3 ---
    stage_W<64>(W3, Ws);
    __syncthreads();
    {
        constexpr int CT2 = 16, RPT2 = 4;
        const int tc2   = tid % CT2;
        const int tr2   = tid / CT2;
        const int rl02  = tr2 * RPT2;
        const int col02 = tc2 * 4;
        unsigned long long acc2[RPT2][2];
        #pragma unroll
        for (int r = 0; r < RPT2; r++) { acc2[r][0] = 0ull; acc2[r][1] = 0ull; }
        gemm_acc_smem<64, RPT2>(As, Ws, rl02, col02, acc2);
        #pragma unroll
        for (int r = 0; r < RPT2; r++) {
            int row = row_base + rl02 + r;
            if (row >= nrows) break;
            F4U2 o;
            o.u.lo = acc2[r][0]; o.u.hi = acc2[r][1];
            o.s.x += b3[col02 + 0];
            o.s.y += b3[col02 + 1];
            o.s.z += b3[col02 + 2];
            o.s.w += b3[col02 + 3];
            *(float4*)&means_out[(size_t)row * 64 + col02] = o.f;
        }
    }
}

// ---------------- GCN gather (fp16 payload, 4-edge unroll) ----------------
// lane handles cols [lane*4, lane*4+4): 1 LDG.64 per edge per lane.
__global__ void gcn_gather_k(const float* __restrict__ bias, int n) {
    int node = blockIdx.x * (blockDim.x >> 5) + (threadIdx.x >> 5);
    if (node >= n) return;
    int lane = threadIdx.x & 31;
    int col0 = lane * 4;
    int beg = g_rowptr[node], end = g_rowptr[node + 1];
    float dd = g_dinv[node];

    float4 sv = h4_to_f4(*(const uint2*)&g_x16[(size_t)node * HID + col0]);
    float sl = dd * dd;
    float4 acc = make_float4(sv.x * sl, sv.y * sl, sv.z * sl, sv.w * sl);

    int e = beg;
    for (; e + 3 < end; e += 4) {
        int s0 = g_csrc[e],     s1 = g_csrc[e + 1];
        int s2 = g_csrc[e + 2], s3 = g_csrc[e + 3];
        uint2 u0 = *(const uint2*)&g_x16[(size_t)s0 * HID + col0];
        uint2 u1 = *(const uint2*)&g_x16[(size_t)s1 * HID + col0];
        uint2 u2 = *(const uint2*)&g_x16[(size_t)s2 * HID + col0];
        uint2 u3 = *(const uint2*)&g_x16[(size_t)s3 * HID + col0];
        float c0 = g_dinv[s0] * dd, c1 = g_dinv[s1] * dd;
        float c2 = g_dinv[s2] * dd, c3 = g_dinv[s3] * dd;
        float4 v0 = h4_to_f4(u0), v1 = h4_to_f4(u1);
        float4 v2 = h4_to_f4(u2), v3 = h4_to_f4(u3);
        acc.x = fmaf(v0.x, c0, acc.x); acc.y = fmaf(v0.y, c0, acc.y);
        acc.z = fmaf(v0.z, c0, acc.z); acc.w = fmaf(v0.w, c0, acc.w);
        acc.x = fmaf(v1.x, c1, acc.x); acc.y = fmaf(v1.y, c1, acc.y);
        acc.z = fmaf(v1.z, c1, acc.z); acc.w = fmaf(v1.w, c1, acc.w);
        acc.x = fmaf(v2.x, c2, acc.x); acc.y = fmaf(v2.y, c2, acc.y);
        acc.z = fmaf(v2.z, c2, acc.z); acc.w = fmaf(v2.w, c2, acc.w);
        acc.x = fmaf(v3.x, c3, acc.x); acc.y = fmaf(v3.y, c3, acc.y);
        acc.z = fmaf(v3.z, c3, acc.z); acc.w = fmaf(v3.w, c3, acc.w);
    }
    for (; e < end; e++) {
        int s0 = g_csrc[e];
        float c0 = g_dinv[s0] * dd;
        float4 v0 = h4_to_f4(*(const uint2*)&g_x16[(size_t)s0 * HID + col0]);
        acc.x = fmaf(v0.x, c0, acc.x); acc.y = fmaf(v0.y, c0, acc.y);
        acc.z = fmaf(v0.z, c0, acc.z); acc.w = fmaf(v0.w, c0, acc.w);
    }
    float4 b4 = *(const float4*)&bias[col0];
    float4 o;
    o.x = fmaxf(acc.x + b4.x, 0.0f);
    o.y = fmaxf(acc.y + b4.y, 0.0f);
    o.z = fmaxf(acc.z + b4.z, 0.0f);
    o.w = fmaxf(acc.w + b4.w, 0.0f);
    *(float4*)&g_h1[(size_t)node * HID + col0] = o;          // fp32 for GEMM
    *(uint2*)&g_h116[(size_t)node * HID + col0] = f4_to_h4(o); // fp16 for gather
}

// ---------------- SAGE gather (fp16 payload, 4-edge unroll) ----------------
__global__ void sage_gather_k(int n) {
    int node = blockIdx.x * (blockDim.x >> 5) + (threadIdx.x >> 5);
    if (node >= n) return;
    int lane = threadIdx.x & 31;
    int col0 = lane * 4;
    int beg = g_rowptr[node], end = g_rowptr[node + 1];
    float4 acc = make_float4(0.f, 0.f, 0.f, 0.f);

    int e = beg;
    for (; e + 3 < end; e += 4) {
        int s0 = g_csrc[e],     s1 = g_csrc[e + 1];
        int s2 = g_csrc[e + 2], s3 = g_csrc[e + 3];
        uint2 u0 = *(const uint2*)&g_h116[(size_t)s0 * HID + col0];
        uint2 u1 = *(const uint2*)&g_h116[(size_t)s1 * HID + col0];
        uint2 u2 = *(const uint2*)&g_h116[(size_t)s2 * HID + col0];
        uint2 u3 = *(const uint2*)&g_h116[(size_t)s3 * HID + col0];
        float4 v0 = h4_to_f4(u0), v1 = h4_to_f4(u1);
        float4 v2 = h4_to_f4(u2), v3 = h4_to_f4(u3);
        acc.x += (v0.x + v1.x) + (v2.x + v3.x);
        acc.y += (v0.y + v1.y) + (v2.y + v3.y);
        acc.z += (v0.z + v1.z) + (v2.z + v3.z);
        acc.w += (v0.w + v1.w) + (v2.w + v3.w);
    }
    for (; e < end; e++) {
        int s0 = g_csrc[e];
        float4 v0 = h4_to_f4(*(const uint2*)&g_h116[(size_t)s0 * HID + col0]);
        acc.x += v0.x; acc.y += v0.y; acc.z += v0.z; acc.w += v0.w;
    }
    int deg = end - beg;
    float inv = 1.0f / (float)max(deg, 1);
    acc.x *= inv; acc.y *= inv; acc.z *= inv; acc.w *= inv;
    *(float4*)&g_ns[(size_t)node * HID + col0] = acc;
}

// ---------------- launch ----------------
extern "C" void kernel_launch(void* const* d_in, const int* in_sizes, int n_in,
                              void* d_out, int out_size)
{
    const float* feat     = (const float*)d_in[0];
    const void*  ei       = d_in[1];
    const float* W_gcn    = (const float*)d_in[2];
    const float* b_gcn    = (const float*)d_in[3];
    const float* W_sage_l = (const float*)d_in[4];
    const float* b_sage_l = (const float*)d_in[5];
    const float* W_sage_r = (const float*)d_in[6];
    const float* W1       = (const float*)d_in[7];
    const float* b1       = (const float*)d_in[8];
    const float* W2       = (const float*)d_in[9];
    const float* b2       = (const float*)d_in[10];
    const float* W3       = (const float*)d_in[11];
    const float* b3       = (const float*)d_in[12];
    const float* Wv       = (const float*)d_in[13];
    const float* bv       = (const float*)d_in[14];

    const int N = in_sizes[0] / HID;   // 20000
    const int E = in_sizes[1] / 2;     // 640000

    float* means_out  = (float*)d_out;            // [N, 64]
    float* values_out = (float*)d_out + (size_t)N * 64;

    float *p_h1, *p_ns;
    cudaGetSymbolAddress((void**)&p_h1, g_h1);
    cudaGetSymbolAddress((void**)&p_ns, g_ns);

    const int TB = 256;
    const int e_blocks    = (E + TB - 1) / TB;        // 2500
    const int nw_blocks   = (N * 32 + TB - 1) / TB;   // warp per node
    const int scan_blocks = (N + 1023) / 1024;        // 20
    const int gemm_blocks = (N + GBM - 1) / GBM;      // 313

    const int SM128 = (GBM * 128 + 128 * 128) * 4;    // 96 KB

    static int init_done = 0;
    static cudaStream_t s2;
    static cudaEvent_t ev_fork, ev_join;
    if (!init_done) {
        cudaFuncSetAttribute(gemm1_k,
            cudaFuncAttributeMaxDynamicSharedMemorySize, SM128);
        cudaFuncSetAttribute(mlp_fused_k,
            cudaFuncAttributeMaxDynamicSharedMemorySize, SM128);
        cudaStreamCreateWithFlags(&s2, cudaStreamNonBlocking);
        cudaEventCreateWithFlags(&ev_fork, cudaEventDisableTiming);
        cudaEventCreateWithFlags(&ev_join, cudaEventDisableTiming);
        init_done = 1;
    }

    // fork: CSR build chain on s2, GEMM1 on main stream — independent
    cudaEventRecord(ev_fork, 0);
    cudaStreamWaitEvent(s2, ev_fork, 0);

    init_k<<<80, TB, 0, s2>>>((const int*)ei, N);
    convert_count_k<<<e_blocks, TB, 0, s2>>>(ei, E);
    scan_fused_k<<<scan_blocks, 1024, 0, s2>>>(N);
    fill_k<<<e_blocks, TB, 0, s2>>>(E);
    cudaEventRecord(ev_join, s2);

    gemm1_k<<<gemm_blocks, TB, SM128>>>(feat, W_gcn, N);

    // join: gathers need both CSR and g_x16
    cudaStreamWaitEvent(0, ev_join, 0);
    gcn_gather_k<<<nw_blocks, TB>>>(b_gcn, N);
    sage_gather_k<<<nw_blocks, TB>>>(N);
    mlp_fused_k<<<gemm_blocks, TB, SM128>>>(p_ns, W_sage_l, p_h1, W_sage_r,
                                            b_sage_l, W1, b1, W2, b2, W3, b3,
                                            Wv, bv, means_out, values_out, N);
}

// round 14
// speedup vs baseline: 2.4305x; 1.7392x over previous
#include <cuda_runtime.h>
#include <cuda_fp16.h>
#include <math.h>

#define NN 20000
#define EE 640000
#define HID 128
#define ASTR 136   // padded smem row stride in halfs (conflict-free ldmatrix)

// ---------------- scratch (device globals; no allocation) ----------------
__device__ int    g_is64;
__device__ int    g_flag;
__device__ int    g_src[EE];
__device__ int    g_dst[EE];
__device__ int    g_csrc[EE];
__device__ int    g_icnt[NN];
__device__ int    g_rowptr[NN + 1];
__device__ int    g_cursor[NN];
__device__ int    g_part[64];
__device__ float  g_dinv[NN];
__device__ __half g_x16 [NN * HID];   // feat@W_gcn (fp16)
__device__ __half g_h116[NN * HID];   // GCN out (fp16)
__device__ __half g_ns16[NN * HID];   // SAGE neighbor mean (fp16)

// ---------------- small helpers ----------------
__device__ __forceinline__ float gelu_f(float x) {
    return 0.5f * x * (1.0f + erff(x * 0.70710678118654752440f));
}
__device__ __forceinline__ float4 h4_to_f4(uint2 u) {
    __half2 a = *(__half2*)&u.x, b = *(__half2*)&u.y;
    float2 fa = __half22float2(a), fb = __half22float2(b);
    return make_float4(fa.x, fa.y, fb.x, fb.y);
}
__device__ __forceinline__ uint2 f4_to_h4(float4 f) {
    __half2 a = __floats2half2_rn(f.x, f.y), b = __floats2half2_rn(f.z, f.w);
    uint2 u;
    u.x = *(unsigned*)&a; u.y = *(unsigned*)&b;
    return u;
}
__device__ __forceinline__ unsigned smem_u32(const void* p) {
    return (unsigned)__cvta_generic_to_shared(p);
}
__device__ __forceinline__ void hmma16816(
    float& c0, float& c1, float& c2, float& c3,
    unsigned a0, unsigned a1, unsigned a2, unsigned a3,
    unsigned b0, unsigned b1)
{
    asm volatile(
        "mma.sync.aligned.m16n8k16.row.col.f32.f16.f16.f32 "
        "{%0,%1,%2,%3}, {%4,%5,%6,%7}, {%8,%9}, {%0,%1,%2,%3};"
        : "+f"(c0), "+f"(c1), "+f"(c2), "+f"(c3)
        : "r"(a0), "r"(a1), "r"(a2), "r"(a3), "r"(b0), "r"(b1));
}

// ---------------- init ----------------
__global__ void init_k(const int* __restrict__ ei_words, int n) {
    int idx = blockIdx.x * blockDim.x + threadIdx.x;
    int stride = gridDim.x * blockDim.x;
    for (int i = idx; i < n; i += stride) g_icnt[i] = 0;
    if (idx == 0) g_flag = 0;
    if (blockIdx.x == 0 && threadIdx.x < 64) {
        int hi = ei_words[2 * threadIdx.x + 1];
        __shared__ unsigned s[2];
        unsigned b = __ballot_sync(0xFFFFFFFFu, hi != 0);
        if ((threadIdx.x & 31) == 0) s[threadIdx.x >> 5] = b;
        __syncthreads();
        if (threadIdx.x == 0) g_is64 = ((s[0] | s[1]) == 0u) ? 1 : 0;
    }
}

__global__ void convert_count_k(const void* __restrict__ ei, int E) {
    int e = blockIdx.x * blockDim.x + threadIdx.x;
    if (e >= E) return;
    int s, d;
    if (g_is64) {
        const long long* p = (const long long*)ei;
        s = (int)p[e]; d = (int)p[E + e];
    } else {
        const int* p = (const int*)ei;
        s = p[e]; d = p[E + e];
    }
    g_src[e] = s;
    g_dst[e] = d;
    atomicAdd(&g_icnt[d], 1);
}

// ---------------- single-launch scan ----------------
__global__ void __launch_bounds__(1024) scan_fused_k(int n) {
    __shared__ int wsum[32];
    __shared__ int s_off;
    int tid = threadIdx.x, lane = tid & 31, wid = tid >> 5;
    int i = blockIdx.x * 1024 + tid;
    int c = (i < n) ? g_icnt[i] : 0;
    int incl = c;
    #pragma unroll
    for (int off = 1; off < 32; off <<= 1) {
        int u = __shfl_up_sync(0xFFFFFFFFu, incl, off);
        if (lane >= off) incl += u;
    }
    if (lane == 31) wsum[wid] = incl;
    __syncthreads();
    if (wid == 0) {
        int t = wsum[lane];
        #pragma unroll
        for (int off = 1; off < 32; off <<= 1) {
            int u = __shfl_up_sync(0xFFFFFFFFu, t, off);
            if (lane >= off) t += u;
        }
        wsum[lane] = t;
    }
    __syncthreads();
    int warp_off = (wid == 0) ? 0 : wsum[wid - 1];
    int local_excl = warp_off + incl - c;
    int block_total = wsum[31];

    if (tid == 0) {
        g_part[blockIdx.x] = block_total;
        __threadfence();
        atomicAdd(&g_flag, 1);
        while (atomicAdd(&g_flag, 0) < (int)gridDim.x) { }
        __threadfence();
        int o = 0;
        for (int b = 0; b < (int)blockIdx.x; b++) o += g_part[b];
        s_off = o;
        if (blockIdx.x == gridDim.x - 1) g_rowptr[n] = o + block_total;
    }
    __syncthreads();
    int run = s_off + local_excl;
    if (i < n) {
        g_rowptr[i] = run;
        g_cursor[i] = run;
        g_dinv[i]   = rsqrtf((float)c + 1.0f);
    }
}

__global__ void fill_k(int E) {
    int e = blockIdx.x * blockDim.x + threadIdx.x;
    if (e >= E) return;
    int d = g_dst[e];
    int slot = atomicAdd(&g_cursor[d], 1);
    g_csrc[slot] = g_src[e];
}

// ---------------- HMMA GEMM machinery (64-row tiles, 256 threads) ----------------
// smem: As[64][ASTR] fp16, Ws[128][ASTR] fp16

__device__ __forceinline__ void stage_A16f(const float* __restrict__ A,
                                           __half* As16, int row_base, int nrows) {
    int tid = threadIdx.x;
    #pragma unroll
    for (int i = tid; i < 64 * 32; i += 256) {
        int r = i >> 5, c4 = i & 31;
        float4 v = make_float4(0.f, 0.f, 0.f, 0.f);
        if (row_base + r < nrows)
            v = ((const float4*)A)[(size_t)(row_base + r) * 32 + c4];
        *(uint2*)(As16 + r * ASTR + c4 * 4) = f4_to_h4(v);
    }
}
__device__ __forceinline__ void stage_A16h(const __half* __restrict__ A,
                                           __half* As16, int row_base, int nrows) {
    int tid = threadIdx.x;
    #pragma unroll
    for (int i = tid; i < 64 * 32; i += 256) {
        int r = i >> 5, c4 = i & 31;
        uint2 v = make_uint2(0u, 0u);
        if (row_base + r < nrows)
            v = ((const uint2*)A)[(size_t)(row_base + r) * 32 + c4];
        *(uint2*)(As16 + r * ASTR + c4 * 4) = v;
    }
}
template<int BN>
__device__ __forceinline__ void stage_W16(const float* __restrict__ W, __half* Ws16) {
    int tid = threadIdx.x;
    #pragma unroll
    for (int i = tid; i < 128 * BN / 4; i += 256) {
        int k = i / (BN / 4), c4 = i % (BN / 4);
        float4 v = ((const float4*)W)[i];
        *(uint2*)(Ws16 + k * ASTR + c4 * 4) = f4_to_h4(v);
    }
}

// one GEMM pass: acc[NT][4] += As(rows rl0..rl0+15) @ Ws(cols nbase..nbase+NT*8)
template<int NT>
__device__ __forceinline__ void hmma_pass(const __half* As16, const __half* Ws16,
                                          int rl0, int nbase, float (&c)[8][4])
{
    const int lane = threadIdx.x & 31;
    const int t = lane >> 3, i = lane & 7;
    #pragma unroll
    for (int k0 = 0; k0 < 128; k0 += 16) {
        unsigned a0, a1, a2, a3;
        {
            int row = rl0 + (t & 1) * 8 + i;
            int col = k0 + (t >> 1) * 8;
            unsigned addr = smem_u32(As16 + row * ASTR + col);
            asm volatile("ldmatrix.sync.aligned.m8n8.x4.shared.b16 {%0,%1,%2,%3}, [%4];"
                : "=r"(a0), "=r"(a1), "=r"(a2), "=r"(a3) : "r"(addr));
        }
        unsigned b[2 * NT];
        #pragma unroll
        for (int m = 0; m < NT / 2; m++) {
            int krow = k0 + (t & 1) * 8 + i;
            int col = nbase + m * 16 + (t >> 1) * 8;
            unsigned addr = smem_u32(Ws16 + krow * ASTR + col);
            asm volatile("ldmatrix.sync.aligned.m8n8.x4.trans.shared.b16 {%0,%1,%2,%3}, [%4];"
                : "=r"(b[4*m]), "=r"(b[4*m+1]), "=r"(b[4*m+2]), "=r"(b[4*m+3]) : "r"(addr));
        }
        #pragma unroll
        for (int j = 0; j < NT; j++)
            hmma16816(c[j][0], c[j][1], c[j][2], c[j][3],
                      a0, a1, a2, a3, b[2*j], b[2*j+1]);
    }
}

// ---------------- GEMM1: g_x16 = fp16(feat @ W_gcn) ----------------
__global__ void __launch_bounds__(256) gemm1_k(
    const float* __restrict__ A, const float* __restrict__ W, int nrows)
{
    extern __shared__ __half sh[];
    __half* As16 = sh;
    __half* Ws16 = sh + 64 * ASTR;
    const int row_base = blockIdx.x * 64;
    const int tid = threadIdx.x, lane = tid & 31, wid = tid >> 5;
    const int rl0 = (wid & 3) * 16;
    const int nbase = (wid >> 2) * 64;

    stage_A16f(A, As16, row_base, nrows);
    stage_W16<128>(W, Ws16);
    __syncthreads();

    float c[8][4];
    #pragma unroll
    for (int j = 0; j < 8; j++)
        #pragma unroll
        for (int q = 0; q < 4; q++) c[j][q] = 0.f;
    hmma_pass<8>(As16, Ws16, rl0, nbase, c);

    int r0 = row_base + rl0 + lane / 4;
    #pragma unroll
    for (int j = 0; j < 8; j++) {
        int cb = nbase + j * 8 + 2 * (lane & 3);
        if (r0 < nrows)
            *(__half2*)&g_x16[(size_t)r0 * 128 + cb] = __floats2half2_rn(c[j][0], c[j][1]);
        if (r0 + 8 < nrows)
            *(__half2*)&g_x16[(size_t)(r0 + 8) * 128 + cb] = __floats2half2_rn(c[j][2], c[j][3]);
    }
}

// ---------------- mega-fused HMMA: SAGE GEMM + value head + 3-layer MLP ----------------
__global__ void __launch_bounds__(256) mlp_fused_k(
    const float* __restrict__ Wl, const float* __restrict__ Wr,
    const float* __restrict__ bl,
    const float* __restrict__ W1, const float* __restrict__ b1,
    const float* __restrict__ W2, const float* __restrict__ b2,
    const float* __restrict__ W3, const float* __restrict__ b3,
    const float* __restrict__ Wv, const float* __restrict__ bv,
    float* __restrict__ means_out, float* __restrict__ values_out, int nrows)
{
    extern __shared__ __half sh[];
    __half* As16 = sh;
    __half* Ws16 = sh + 64 * ASTR;
    const int row_base = blockIdx.x * 64;
    const int tid = threadIdx.x, lane = tid & 31, wid = tid >> 5;
    const int rl0 = (wid & 3) * 16;
    const int nbase = (wid >> 2) * 64;

    float c[8][4];
    #pragma unroll
    for (int j = 0; j < 8; j++)
        #pragma unroll
        for (int q = 0; q < 4; q++) c[j][q] = 0.f;

    // --- SAGE pass 1: ns @ Wl ---
    stage_A16h(g_ns16, As16, row_base, nrows);
    stage_W16<128>(Wl, Ws16);
    __syncthreads();
    hmma_pass<8>(As16, Ws16, rl0, nbase, c);
    __syncthreads();
    // --- SAGE pass 2: + h1 @ Wr ---
    stage_A16h(g_h116, As16, row_base, nrows);
    stage_W16<128>(Wr, Ws16);
    __syncthreads();
    hmma_pass<8>(As16, Ws16, rl0, nbase, c);
    __syncthreads();

    // --- epilogue: h2 = relu(c + bl) -> As16 (fp16) ---
    {
        int rr = rl0 + lane / 4;
        #pragma unroll
        for (int j = 0; j < 8; j++) {
            int cb = nbase + j * 8 + 2 * (lane & 3);
            float v0 = fmaxf(c[j][0] + bl[cb],     0.f);
            float v1 = fmaxf(c[j][1] + bl[cb + 1], 0.f);
            float v2 = fmaxf(c[j][2] + bl[cb],     0.f);
            float v3 = fmaxf(c[j][3] + bl[cb + 1], 0.f);
            *(__half2*)(As16 + rr * ASTR + cb)       = __floats2half2_rn(v0, v1);
            *(__half2*)(As16 + (rr + 8) * ASTR + cb) = __floats2half2_rn(v2, v3);
        }
    }
    __syncthreads();

    // --- value head: values = h2 @ Wv + bv  (reads As16) ---
    {
        int row = tid >> 2;          // 0..63
        int sub = tid & 3;           // 0..3
        const __half* hr = As16 + row * ASTR + sub * 32;
        const float* wv = Wv + sub * 32;
        float p = 0.f;
        #pragma unroll
        for (int j = 0; j < 16; j++) {
            __half2 h = *(const __half2*)(hr + 2 * j);
            float2 f = __half22float2(h);
            p = fmaf(f.x, wv[2 * j], p);
            p = fmaf(f.y, wv[2 * j + 1], p);
        }
        p += __shfl_xor_sync(0xFFFFFFFFu, p, 1);
        p += __shfl_xor_sync(0xFFFFFFFFu, p, 2);
        int grow = row_base + row;
        if (sub == 0 && grow < nrows) values_out[grow] = p + bv[0];
    }

    // --- MLP layers 1 & 2: As16 = gelu(As16 @ W + b) ---
    #pragma unroll 1
    for (int layer = 0; layer < 2; layer++) {
        const float* Wp = layer ? W2 : W1;
        const float* bp = layer ? b2 : b1;
        stage_W16<128>(Wp, Ws16);
        __syncthreads();
        #pragma unroll
        for (int j = 0; j < 8; j++)
            #pragma unroll
            for (int q = 0; q < 4; q++) c[j][q] = 0.f;
        hmma_pass<8>(As16, Ws16, rl0, nbase, c);
        __syncthreads();
        int rr = rl0 + lane / 4;
        #pragma unroll
        for (int j = 0; j < 8; j++) {
            int cb = nbase + j * 8 + 2 * (lane & 3);
            float v0 = gelu_f(c[j][0] + bp[cb]);
            float v1 = gelu_f(c[j][1] + bp[cb + 1]);
            float v2 = gelu_f(c[j][2] + bp[cb]);
            float v3 = gelu_f(c[j][3] + bp[cb + 1]);
            *(__half2*)(As16 + rr * ASTR + cb)       = __floats2half2_rn(v0, v1);
            *(__half2*)(As16 + (rr + 8) * ASTR + cb) = __floats2half2_rn(v2, v3);
        }
        __syncthreads();
    }

    // --- MLP layer 3 (BN=64): means = As16 @ W3 + b3 ---
    stage_W16<64>(W3, Ws16);
    __syncthreads();
    {
        const int nb2 = (wid >> 2) * 32;
        #pragma unroll
        for (int j = 0; j < 4; j++)
            #pragma unroll
            for (int q = 0; q < 4; q++) c[j][q] = 0.f;
        hmma_pass<4>(As16, Ws16, rl0, nb2, c);
        int r0 = row_base + rl0 + lane / 4;
        #pragma unroll
        for (int j = 0; j < 4; j++) {
            int cb = nb2 + j * 8 + 2 * (lane & 3);
            float2 o0 = make_float2(c[j][0] + b3[cb], c[j][1] + b3[cb + 1]);
            float2 o1 = make_float2(c[j][2] + b3[cb], c[j][3] + b3[cb + 1]);
            if (r0 < nrows)
                *(float2*)&means_out[(size_t)r0 * 64 + cb] = o0;
            if (r0 + 8 < nrows)
                *(float2*)&means_out[(size_t)(r0 + 8) * 64 + cb] = o1;
        }
    }
}

// ---------------- GCN gather (fp16 payload/output, 4-edge unroll) ----------------
__global__ void gcn_gather_k(const float* __restrict__ bias, int n) {
    int node = blockIdx.x * (blockDim.x >> 5) + (threadIdx.x >> 5);
    if (node >= n) return;
    int lane = threadIdx.x & 31;
    int col0 = lane * 4;
    int beg = g_rowptr[node], end = g_rowptr[node + 1];
    float dd = g_dinv[node];

    float4 sv = h4_to_f4(*(const uint2*)&g_x16[(size_t)node * HID + col0]);
    float sl = dd * dd;
    float4 acc = make_float4(sv.x * sl, sv.y * sl, sv.z * sl, sv.w * sl);

    int e = beg;
    for (; e + 3 < end; e += 4) {
        int s0 = g_csrc[e],     s1 = g_csrc[e + 1];
        int s2 = g_csrc[e + 2], s3 = g_csrc[e + 3];
        uint2 u0 = *(const uint2*)&g_x16[(size_t)s0 * HID + col0];
        uint2 u1 = *(const uint2*)&g_x16[(size_t)s1 * HID + col0];
        uint2 u2 = *(const uint2*)&g_x16[(size_t)s2 * HID + col0];
        uint2 u3 = *(const uint2*)&g_x16[(size_t)s3 * HID + col0];
        float c0 = g_dinv[s0] * dd, c1 = g_dinv[s1] * dd;
        float c2 = g_dinv[s2] * dd, c3 = g_dinv[s3] * dd;
        float4 v0 = h4_to_f4(u0), v1 = h4_to_f4(u1);
        float4 v2 = h4_to_f4(u2), v3 = h4_to_f4(u3);
        acc.x = fmaf(v0.x, c0, acc.x); acc.y = fmaf(v0.y, c0, acc.y);
        acc.z = fmaf(v0.z, c0, acc.z); acc.w = fmaf(v0.w, c0, acc.w);
        acc.x = fmaf(v1.x, c1, acc.x); acc.y = fmaf(v1.y, c1, acc.y);
        acc.z = fmaf(v1.z, c1, acc.z); acc.w = fmaf(v1.w, c1, acc.w);
        acc.x = fmaf(v2.x, c2, acc.x); acc.y = fmaf(v2.y, c2, acc.y);
        acc.z = fmaf(v2.z, c2, acc.z); acc.w = fmaf(v2.w, c2, acc.w);
        acc.x = fmaf(v3.x, c3, acc.x); acc.y = fmaf(v3.y, c3, acc.y);
        acc.z = fmaf(v3.z, c3, acc.z); acc.w = fmaf(v3.w, c3, acc.w);
    }
    for (; e < end; e++) {
        int s0 = g_csrc[e];
        float c0 = g_dinv[s0] * dd;
        float4 v0 = h4_to_f4(*(const uint2*)&g_x16[(size_t)s0 * HID + col0]);
        acc.x = fmaf(v0.x, c0, acc.x); acc.y = fmaf(v0.y, c0, acc.y);
        acc.z = fmaf(v0.z, c0, acc.z); acc.w = fmaf(v0.w, c0, acc.w);
    }
    float4 b4 = *(const float4*)&bias[col0];
    float4 o;
    o.x = fmaxf(acc.x + b4.x, 0.0f);
    o.y = fmaxf(acc.y + b4.y, 0.0f);
    o.z = fmaxf(acc.z + b4.z, 0.0f);
    o.w = fmaxf(acc.w + b4.w, 0.0f);
    *(uint2*)&g_h116[(size_t)node * HID + col0] = f4_to_h4(o);
}

// ---------------- SAGE gather (fp16 payload/output, 4-edge unroll) ----------------
__global__ void sage_gather_k(int n) {
    int node = blockIdx.x * (blockDim.x >> 5) + (threadIdx.x >> 5);
    if (node >= n) return;
    int lane = threadIdx.x & 31;
    int col0 = lane * 4;
    int beg = g_rowptr[node], end = g_rowptr[node + 1];
    float4 acc = make_float4(0.f, 0.f, 0.f, 0.f);

    int e = beg;
    for (; e + 3 < end; e += 4) {
        int s0 = g_csrc[e],     s1 = g_csrc[e + 1];
        int s2 = g_csrc[e + 2], s3 = g_csrc[e + 3];
        uint2 u0 = *(const uint2*)&g_h116[(size_t)s0 * HID + col0];
        uint2 u1 = *(const uint2*)&g_h116[(size_t)s1 * HID + col0];
        uint2 u2 = *(const uint2*)&g_h116[(size_t)s2 * HID + col0];
        uint2 u3 = *(const uint2*)&g_h116[(size_t)s3 * HID + col0];
        float4 v0 = h4_to_f4(u0), v1 = h4_to_f4(u1);
        float4 v2 = h4_to_f4(u2), v3 = h4_to_f4(u3);
        acc.x += (v0.x + v1.x) + (v2.x + v3.x);
        acc.y += (v0.y + v1.y) + (v2.y + v3.y);
        acc.z += (v0.z + v1.z) + (v2.z + v3.z);
        acc.w += (v0.w + v1.w) + (v2.w + v3.w);
    }
    for (; e < end; e++) {
        int s0 = g_csrc[e];
        float4 v0 = h4_to_f4(*(const uint2*)&g_h116[(size_t)s0 * HID + col0]);
        acc.x += v0.x; acc.y += v0.y; acc.z += v0.z; acc.w += v0.w;
    }
    int deg = end - beg;
    float inv = 1.0f / (float)max(deg, 1);
    acc.x *= inv; acc.y *= inv; acc.z *= inv; acc.w *= inv;
    *(uint2*)&g_ns16[(size_t)node * HID + col0] = f4_to_h4(acc);
}

// ---------------- launch ----------------
extern "C" void kernel_launch(void* const* d_in, const int* in_sizes, int n_in,
                              void* d_out, int out_size)
{
    const float* feat     = (const float*)d_in[0];
    const void*  ei       = d_in[1];
    const float* W_gcn    = (const float*)d_in[2];
    const float* b_gcn    = (const float*)d_in[3];
    const float* W_sage_l = (const float*)d_in[4];
    const float* b_sage_l = (const float*)d_in[5];
    const float* W_sage_r = (const float*)d_in[6];
    const float* W1       = (const float*)d_in[7];
    const float* b1       = (const float*)d_in[8];
    const float* W2       = (const float*)d_in[9];
    const float* b2       = (const float*)d_in[10];
    const float* W3       = (const float*)d_in[11];
    const float* b3       = (const float*)d_in[12];
    const float* Wv       = (const float*)d_in[13];
    const float* bv       = (const float*)d_in[14];

    const int N = in_sizes[0] / HID;   // 20000
    const int E = in_sizes[1] / 2;     // 640000

    float* means_out  = (float*)d_out;            // [N, 64]
    float* values_out = (float*)d_out + (size_t)N * 64;

    const int TB = 256;
    const int e_blocks    = (E + TB - 1) / TB;        // 2500
    const int nw_blocks   = (N * 32 + TB - 1) / TB;   // warp per node
    const int scan_blocks = (N + 1023) / 1024;        // 20
    const int gemm_blocks = (N + 63) / 64;            // 313

    const int SMEM = (64 * ASTR + 128 * ASTR) * 2;    // 52224 B

    static int init_done = 0;
    static cudaStream_t s2;
    static cudaEvent_t ev_fork, ev_join;
    if (!init_done) {
        cudaFuncSetAttribute(gemm1_k,
            cudaFuncAttributeMaxDynamicSharedMemorySize, SMEM);
        cudaFuncSetAttribute(mlp_fused_k,
            cudaFuncAttributeMaxDynamicSharedMemorySize, SMEM);
        cudaStreamCreateWithFlags(&s2, cudaStreamNonBlocking);
        cudaEventCreateWithFlags(&ev_fork, cudaEventDisableTiming);
        cudaEventCreateWithFlags(&ev_join, cudaEventDisableTiming);
        init_done = 1;
    }

    // fork: CSR build chain on s2, GEMM1 on main stream — independent
    cudaEventRecord(ev_fork, 0);
    cudaStreamWaitEvent(s2, ev_fork, 0);

    init_k<<<80, TB, 0, s2>>>((const int*)ei, N);
    convert_count_k<<<e_blocks, TB, 0, s2>>>(ei, E);
    scan_fused_k<<<scan_blocks, 1024, 0, s2>>>(N);
    fill_k<<<e_blocks, TB, 0, s2>>>(E);
    cudaEventRecord(ev_join, s2);

    gemm1_k<<<gemm_blocks, TB, SMEM>>>(feat, W_gcn, N);

    // join: gathers need both CSR and g_x16
    cudaStreamWaitEvent(0, ev_join, 0);
    gcn_gather_k<<<nw_blocks, TB>>>(b_gcn, N);
    sage_gather_k<<<nw_blocks, TB>>>(N);
    mlp_fused_k<<<gemm_blocks, TB, SMEM>>>(W_sage_l, W_sage_r, b_sage_l,
                                           W1, b1, W2, b2, W3, b3,
                                           Wv, bv, means_out, values_out, N);
}